// round 10
// baseline (speedup 1.0000x reference)
#include <cuda_runtime.h>
#include <cuda_bf16.h>
#include <math.h>
#include <stdint.h>

#define TT     4096      // total tokens B*S
#define SEQ    1024
#define BATCH  4
#define HID    4096
#define NH     32
#define NKV    8
#define HD     128
#define QKVN   6144      // NH*HD + 2*NKV*HD
#define NSLOTS 8192
#define ROT    64
#define KTOT   4096      // logical GEMM K (= HID)
#define KP     12288     // expanded K: [seg0 | seg1 | seg2]

// ---------------------------------------------------------------------------
// Scratch (no cudaMalloc allowed)
// ---------------------------------------------------------------------------
__device__ float g_qkv[(size_t)TT * QKVN];               // fp32 qkv activations
__device__ float g_ctx[(size_t)TT * HID];                // fp32 attention context
__device__ __nv_bfloat16 g_aexp    [(size_t)TT   * KP];  // hidden  [hi|lo|hi]
__device__ __nv_bfloat16 g_wqkv_exp[(size_t)QKVN * KP];  // w_qkv   [hi|hi|lo]
__device__ __nv_bfloat16 g_wo_exp  [(size_t)HID  * KP];  // w_o     [hi|hi|lo]
__device__ __nv_bfloat16 g_ctx_exp [(size_t)TT   * KP];  // ctx     [hi|lo|hi]

// ---------------------------------------------------------------------------
// helpers
// ---------------------------------------------------------------------------
__device__ __forceinline__ uint32_t smem_u32(const void* p) {
    uint32_t a;
    asm("{ .reg .u64 t; cvta.to.shared.u64 t, %1; cvt.u32.u64 %0, t; }" : "=r"(a) : "l"(p));
    return a;
}
__device__ __forceinline__ void cp_async16(uint32_t dst, const void* src) {
    asm volatile("cp.async.cg.shared.global [%0], [%1], 16;" :: "r"(dst), "l"(src));
}
__device__ __forceinline__ void ldsm4(uint32_t* r, uint32_t addr) {
    asm volatile("ldmatrix.sync.aligned.m8n8.x4.shared.b16 {%0,%1,%2,%3}, [%4];"
        : "=r"(r[0]), "=r"(r[1]), "=r"(r[2]), "=r"(r[3]) : "r"(addr));
}
__device__ __forceinline__ void ldsm4t(uint32_t* r, uint32_t addr) {
    asm volatile("ldmatrix.sync.aligned.m8n8.x4.trans.shared.b16 {%0,%1,%2,%3}, [%4];"
        : "=r"(r[0]), "=r"(r[1]), "=r"(r[2]), "=r"(r[3]) : "r"(addr));
}
__device__ __forceinline__ void mma16816(float* c, const uint32_t* a, uint32_t b0, uint32_t b1) {
    asm volatile(
        "mma.sync.aligned.m16n8k16.row.col.f32.bf16.bf16.f32 "
        "{%0,%1,%2,%3}, {%4,%5,%6,%7}, {%8,%9}, {%0,%1,%2,%3};"
        : "+f"(c[0]), "+f"(c[1]), "+f"(c[2]), "+f"(c[3])
        : "r"(a[0]), "r"(a[1]), "r"(a[2]), "r"(a[3]), "r"(b0), "r"(b1));
}
__device__ __forceinline__ uint32_t packbf2(float lo, float hi) {
    __nv_bfloat162 v(__float2bfloat16(lo), __float2bfloat16(hi));
    return *(uint32_t*)&v;
}

// ---------------------------------------------------------------------------
// fp32 -> triple-segment bf16 expansion (GEMM operands)
// A-type rows (activations): [hi | lo | hi] ; B-type rows (weights): [hi | hi | lo]
// ---------------------------------------------------------------------------
__global__ void expand3(const float* __restrict__ src, int rows, int mode) {
    __nv_bfloat16* dst = (mode == 0) ? g_aexp : (mode == 1) ? g_wqkv_exp
                        : (mode == 2) ? g_wo_exp : g_ctx_exp;
    const float* s = (mode == 3) ? g_ctx : src;
    int idx = blockIdx.x * blockDim.x + threadIdx.x;
    int total = rows * (KTOT / 4);
    if (idx >= total) return;
    int row = idx >> 10;
    int c4  = idx & 1023;
    float4 v = *(const float4*)(s + (size_t)row * KTOT + c4 * 4);
    __nv_bfloat16 h0 = __float2bfloat16(v.x);
    __nv_bfloat16 h1 = __float2bfloat16(v.y);
    __nv_bfloat16 h2 = __float2bfloat16(v.z);
    __nv_bfloat16 h3 = __float2bfloat16(v.w);
    __nv_bfloat16 l0 = __float2bfloat16(v.x - __bfloat162float(h0));
    __nv_bfloat16 l1 = __float2bfloat16(v.y - __bfloat162float(h1));
    __nv_bfloat16 l2 = __float2bfloat16(v.z - __bfloat162float(h2));
    __nv_bfloat16 l3 = __float2bfloat16(v.w - __bfloat162float(h3));
    __nv_bfloat162 hA(h0, h1), hB(h2, h3), lA(l0, l1), lB(l2, l3);
    size_t base = (size_t)row * KP + c4 * 4;
    __nv_bfloat162* d0 = (__nv_bfloat162*)(dst + base);
    __nv_bfloat162* d1 = (__nv_bfloat162*)(dst + base + KTOT);
    __nv_bfloat162* d2 = (__nv_bfloat162*)(dst + base + 2 * KTOT);
    d0[0] = hA; d0[1] = hB;
    bool atype = (mode == 0 || mode == 3);
    if (atype) { d1[0] = lA; d1[1] = lB; d2[0] = hA; d2[1] = hB; }
    else       { d1[0] = hA; d1[1] = hB; d2[0] = lA; d2[1] = lB; }
}

// ---------------------------------------------------------------------------
// bf16 mma.sync GEMM: C[M,N] = A'[M,KP] @ B'[N,KP]^T, fp32 accumulate.
// CTA tile 128(M) x 256(N), BK=32, 4-stage cp.async pipeline.
// 8 warps in 2(M) x 4(N) grid -> 64x64 warp tile (smem-traffic balanced:
// 16.4 MAC/B vs 16 needed for the 128 B/cyc crossbar at ~2048 MAC/cyc).
// ---------------------------------------------------------------------------
#define BM 128
#define BN 256
#define BK 32
#define STAGES 4
#define ROWB 80                          // padded row bytes (40 bf16, 64 data)
#define ATILEB (128 * ROWB)              // 10240
#define BTILEB (256 * ROWB)              // 20480
#define STAGEB (ATILEB + BTILEB)         // 30720
#define GEMM_SMEM (STAGES * STAGEB)      // 122880
#define NCH (KP / BK)                    // 384

__device__ __forceinline__ void load_stage(const __nv_bfloat16* __restrict__ A,
                                           const __nv_bfloat16* __restrict__ B,
                                           int bm, int bn, int k0,
                                           uint32_t stage_base, int tid) {
    #pragma unroll
    for (int it = 0; it < 6; it++) {
        int idx = tid + it * 256;          // 0..1535
        const __nv_bfloat16* src;
        uint32_t dst;
        if (idx < 512) {                   // A: 128 rows x 4 chunks
            int r = idx >> 2, c = idx & 3;
            src = A + (size_t)(bm + r) * KP + k0 + c * 8;
            dst = stage_base + r * ROWB + c * 16;
        } else {                           // B: 256 rows x 4 chunks
            int i2 = idx - 512;
            int r = i2 >> 2, c = i2 & 3;
            src = B + (size_t)(bn + r) * KP + k0 + c * 8;
            dst = stage_base + ATILEB + r * ROWB + c * 16;
        }
        cp_async16(dst, src);
    }
    asm volatile("cp.async.commit_group;" ::: "memory");
}

__global__ __launch_bounds__(256, 1)
void gemm_bf16(int mode, float* __restrict__ outp) {
    extern __shared__ char smem[];
    const uint32_t sb = smem_u32(smem);
    const int tid  = threadIdx.x;
    const int wid  = tid >> 5;
    const int lane = tid & 31;
    const int wm   = wid >> 2;         // 0..1, 64 rows each
    const int wn   = wid & 3;          // 0..3, 64 cols each

    const __nv_bfloat16* A;
    const __nv_bfloat16* B;
    float* C;
    int Ntot;
    if (mode == 0) { A = g_aexp;    B = g_wqkv_exp; C = g_qkv; Ntot = QKVN; }
    else           { A = g_ctx_exp; B = g_wo_exp;   C = outp;  Ntot = HID;  }

    const int bn = blockIdx.x * BN;
    const int bm = blockIdx.y * BM;

    float acc[4][8][4];
    #pragma unroll
    for (int mi = 0; mi < 4; mi++)
        #pragma unroll
        for (int ni = 0; ni < 8; ni++)
            #pragma unroll
            for (int q = 0; q < 4; q++) acc[mi][ni][q] = 0.f;

    // LDSM per-thread base offsets
    const uint32_t a_off = (uint32_t)(wm * 64 + (lane & 15)) * ROWB + (lane >> 4) * 16;
    const uint32_t b_off = (uint32_t)(wn * 64 + (lane & 7) + ((lane >> 4) & 1) * 8) * ROWB
                         + ((lane >> 3) & 1) * 16;

    load_stage(A, B, bm, bn, 0,      sb,              tid);
    load_stage(A, B, bm, bn, BK,     sb + STAGEB,     tid);
    load_stage(A, B, bm, bn, 2 * BK, sb + 2 * STAGEB, tid);

    #pragma unroll 1
    for (int i = 0; i < NCH; i++) {
        if (i < NCH - 2)       asm volatile("cp.async.wait_group 2;" ::: "memory");
        else if (i == NCH - 2) asm volatile("cp.async.wait_group 1;" ::: "memory");
        else                   asm volatile("cp.async.wait_group 0;" ::: "memory");
        __syncthreads();

        if (i + 3 < NCH)
            load_stage(A, B, bm, bn, (i + 3) * BK, sb + ((i + 3) & 3) * STAGEB, tid);

        const uint32_t As = sb + (i & 3) * STAGEB;
        const uint32_t Bs = As + ATILEB;

        #pragma unroll
        for (int ks = 0; ks < 2; ks++) {
            const uint32_t koff = ks * 32;
            uint32_t a[4][4];
            #pragma unroll
            for (int mi = 0; mi < 4; mi++)
                ldsm4(a[mi], As + a_off + (uint32_t)mi * (16 * ROWB) + koff);
            uint32_t b[4][4];
            #pragma unroll
            for (int p = 0; p < 4; p++)
                ldsm4(b[p], Bs + b_off + (uint32_t)p * (16 * ROWB) + koff);
            #pragma unroll
            for (int mi = 0; mi < 4; mi++)
                #pragma unroll
                for (int ni = 0; ni < 8; ni++)
                    mma16816(acc[mi][ni], a[mi],
                             b[ni >> 1][(ni & 1) * 2], b[ni >> 1][(ni & 1) * 2 + 1]);
        }
    }

    // epilogue
    const int crow0 = bm + wm * 64 + (lane >> 2);
    const int ccol  = bn + wn * 64 + (lane & 3) * 2;
    #pragma unroll
    for (int mi = 0; mi < 4; mi++) {
        #pragma unroll
        for (int ni = 0; ni < 8; ni++) {
            float* p0 = C + (size_t)(crow0 + mi * 16)     * Ntot + ccol + ni * 8;
            float* p1 = C + (size_t)(crow0 + mi * 16 + 8) * Ntot + ccol + ni * 8;
            *(float2*)p0 = make_float2(acc[mi][ni][0], acc[mi][ni][1]);
            *(float2*)p1 = make_float2(acc[mi][ni][2], acc[mi][ni][3]);
        }
    }
}

// ---------------------------------------------------------------------------
// Cache copy + RoPE + scatters (unchanged)
// ---------------------------------------------------------------------------
__global__ void copy_caches(const float4* __restrict__ kc, const float4* __restrict__ vc,
                            float4* __restrict__ okc, float4* __restrict__ ovc, int n4) {
    int i = blockIdx.x * blockDim.x + threadIdx.x;
    if (i < n4) { okc[i] = kc[i]; ovc[i] = vc[i]; }
}

__global__ void rope_scatter(const float* __restrict__ cosb,
                             const float* __restrict__ sinb, const int* __restrict__ slots,
                             float* __restrict__ okc) {
    int idx = blockIdx.x * blockDim.x + threadIdx.x;
    if (idx >= TT * (NH + NKV) * ROT) return;
    int r    = idx & (ROT - 1);
    int head = (idx >> 6) % (NH + NKV);
    int t    = idx / (ROT * (NH + NKV));
    float c = cosb[t * ROT + r];
    float s = sinb[t * ROT + r];
    float* base = g_qkv + (size_t)t * QKVN + head * HD;
    float x1 = base[r];
    float x2 = base[r + ROT];
    float o1 = x1 * c - x2 * s;
    float o2 = x1 * s + x2 * c;
    base[r] = o1;
    base[r + ROT] = o2;
    if (head >= NH && okc != nullptr) {
        int kvh = head - NH;
        float* kcp = okc + (size_t)slots[t] * (NKV * HD) + kvh * HD;
        kcp[r] = o1;
        kcp[r + ROT] = o2;
    }
}

__global__ void v_scatter(const int* __restrict__ slots, float* __restrict__ ovc) {
    int idx = blockIdx.x * blockDim.x + threadIdx.x;
    if (idx >= TT * NKV * HD) return;
    int d   = idx & (HD - 1);
    int kvh = (idx >> 7) & (NKV - 1);
    int t   = idx >> 10;
    ovc[(size_t)slots[t] * (NKV * HD) + kvh * HD + d] =
        g_qkv[(size_t)t * QKVN + (NH + NKV) * HD + kvh * HD + d];
}

// ---------------------------------------------------------------------------
// Tensor-core flash attention (bf16 split, fp32 accumulate) — unchanged.
// ---------------------------------------------------------------------------
#define ASTR 272
#define QH_OFF 0
#define QL_OFF (128 * ASTR)
#define KH_OFF (2 * 128 * ASTR)
#define KL_OFF (KH_OFF + 64 * ASTR)
#define VH_OFF (KL_OFF + 64 * ASTR)
#define VL_OFF (VH_OFF + 64 * ASTR)
#define ATT_SMEM (VL_OFF + 64 * ASTR)

__global__ __launch_bounds__(256, 1)
void attn_mma() {
    extern __shared__ char sm[];
    const uint32_t sb = smem_u32(sm);
    const int qt  = blockIdx.x;
    const int h   = blockIdx.y;
    const int b   = blockIdx.z;
    const int kvh = h >> 2;
    const int tid  = threadIdx.x;
    const int wid  = tid >> 5;
    const int lane = tid & 31;
    const float qscale = 0.08838834764831845f * 1.4426950408889634f;

    const float* qbase = g_qkv + (size_t)(b * SEQ + qt * 128) * QKVN + h * HD;
    for (int i = tid; i < 128 * 32; i += 256) {
        int r = i >> 5, c = i & 31;
        float4 v = *(const float4*)(qbase + (size_t)r * QKVN + c * 4);
        v.x *= qscale; v.y *= qscale; v.z *= qscale; v.w *= qscale;
        __nv_bfloat16 h0 = __float2bfloat16(v.x), h1 = __float2bfloat16(v.y);
        __nv_bfloat16 h2 = __float2bfloat16(v.z), h3 = __float2bfloat16(v.w);
        __nv_bfloat16 l0 = __float2bfloat16(v.x - __bfloat162float(h0));
        __nv_bfloat16 l1 = __float2bfloat16(v.y - __bfloat162float(h1));
        __nv_bfloat16 l2 = __float2bfloat16(v.z - __bfloat162float(h2));
        __nv_bfloat16 l3 = __float2bfloat16(v.w - __bfloat162float(h3));
        __nv_bfloat162* dh = (__nv_bfloat162*)(sm + QH_OFF + r * ASTR + c * 8);
        __nv_bfloat162* dl = (__nv_bfloat162*)(sm + QL_OFF + r * ASTR + c * 8);
        dh[0] = __nv_bfloat162(h0, h1); dh[1] = __nv_bfloat162(h2, h3);
        dl[0] = __nv_bfloat162(l0, l1); dl[1] = __nv_bfloat162(l2, l3);
    }

    float acc_o[16][4];
    #pragma unroll
    for (int f = 0; f < 16; f++)
        #pragma unroll
        for (int q = 0; q < 4; q++) acc_o[f][q] = 0.f;
    float m0 = -INFINITY, m1 = -INFINITY, l0 = 0.f, l1 = 0.f;

    const float* kb0 = g_qkv + (size_t)(b * SEQ) * QKVN + NH * HD + kvh * HD;
    const float* vb0 = kb0 + NKV * HD;
    const int qrow0 = qt * 128 + 16 * wid + (lane >> 2);

    const uint32_t a_off = (uint32_t)(16 * wid + (lane & 15)) * ASTR + (lane >> 4) * 16;
    const uint32_t kb_off = (uint32_t)((lane & 7) + ((lane >> 4) & 1) * 8) * ASTR
                          + ((lane >> 3) & 1) * 16;
    const uint32_t v_off = (uint32_t)(lane & 15) * ASTR + (lane >> 4) * 16;

    const int nkt = 2 * qt + 2;
    for (int kt = 0; kt < nkt; kt++) {
        __syncthreads();
        for (int i = tid; i < 64 * 32 * 2; i += 256) {
            int ten = i >> 11;
            int r = (i >> 5) & 63, c = i & 31;
            const float* src = (ten ? vb0 : kb0) + (size_t)(kt * 64 + r) * QKVN + c * 4;
            float4 v = *(const float4*)src;
            __nv_bfloat16 h0 = __float2bfloat16(v.x), h1 = __float2bfloat16(v.y);
            __nv_bfloat16 h2 = __float2bfloat16(v.z), h3 = __float2bfloat16(v.w);
            __nv_bfloat16 e0 = __float2bfloat16(v.x - __bfloat162float(h0));
            __nv_bfloat16 e1 = __float2bfloat16(v.y - __bfloat162float(h1));
            __nv_bfloat16 e2 = __float2bfloat16(v.z - __bfloat162float(h2));
            __nv_bfloat16 e3 = __float2bfloat16(v.w - __bfloat162float(h3));
            int hof = (ten ? VH_OFF : KH_OFF) + r * ASTR + c * 8;
            int lof = (ten ? VL_OFF : KL_OFF) + r * ASTR + c * 8;
            __nv_bfloat162* dh = (__nv_bfloat162*)(sm + hof);
            __nv_bfloat162* dl = (__nv_bfloat162*)(sm + lof);
            dh[0] = __nv_bfloat162(h0, h1); dh[1] = __nv_bfloat162(h2, h3);
            dl[0] = __nv_bfloat162(e0, e1); dl[1] = __nv_bfloat162(e2, e3);
        }
        __syncthreads();

        float s[8][4];
        #pragma unroll
        for (int j = 0; j < 8; j++)
            #pragma unroll
            for (int q = 0; q < 4; q++) s[j][q] = 0.f;

        #pragma unroll
        for (int kk = 0; kk < 8; kk++) {
            uint32_t ah[4], al[4];
            ldsm4(ah, sb + QH_OFF + a_off + kk * 32);
            ldsm4(al, sb + QL_OFF + a_off + kk * 32);
            uint32_t bh[4][4], bl[4][4];
            #pragma unroll
            for (int p = 0; p < 4; p++) {
                ldsm4(bh[p], sb + KH_OFF + kb_off + (uint32_t)p * (16 * ASTR) + kk * 32);
                ldsm4(bl[p], sb + KL_OFF + kb_off + (uint32_t)p * (16 * ASTR) + kk * 32);
            }
            #pragma unroll
            for (int p = 0; p < 4; p++)
                #pragma unroll
                for (int q = 0; q < 2; q++) {
                    int j = p * 2 + q;
                    mma16816(s[j], ah, bh[p][q * 2], bh[p][q * 2 + 1]);
                    mma16816(s[j], al, bh[p][q * 2], bh[p][q * 2 + 1]);
                    mma16816(s[j], ah, bl[p][q * 2], bl[p][q * 2 + 1]);
                }
        }

        if (kt >= 2 * qt) {
            #pragma unroll
            for (int j = 0; j < 8; j++) {
                int c0 = kt * 64 + 8 * j + 2 * (lane & 3);
                if (c0     > qrow0)     s[j][0] = -INFINITY;
                if (c0 + 1 > qrow0)     s[j][1] = -INFINITY;
                if (c0     > qrow0 + 8) s[j][2] = -INFINITY;
                if (c0 + 1 > qrow0 + 8) s[j][3] = -INFINITY;
            }
        }
        float tm0 = -INFINITY, tm1 = -INFINITY;
        #pragma unroll
        for (int j = 0; j < 8; j++) {
            tm0 = fmaxf(tm0, fmaxf(s[j][0], s[j][1]));
            tm1 = fmaxf(tm1, fmaxf(s[j][2], s[j][3]));
        }
        tm0 = fmaxf(tm0, __shfl_xor_sync(0xffffffffu, tm0, 1));
        tm0 = fmaxf(tm0, __shfl_xor_sync(0xffffffffu, tm0, 2));
        tm1 = fmaxf(tm1, __shfl_xor_sync(0xffffffffu, tm1, 1));
        tm1 = fmaxf(tm1, __shfl_xor_sync(0xffffffffu, tm1, 2));
        float mn0 = fmaxf(m0, tm0), mn1 = fmaxf(m1, tm1);
        float sc0 = exp2f(m0 - mn0), sc1 = exp2f(m1 - mn1);

        uint32_t ap[4][4], apl[4][4];
        float ps0 = 0.f, ps1 = 0.f;
        #pragma unroll
        for (int t = 0; t < 4; t++) {
            #pragma unroll
            for (int q = 0; q < 2; q++) {
                int j = t * 2 + q;
                float p0 = exp2f(s[j][0] - mn0);
                float p1 = exp2f(s[j][1] - mn0);
                float p2 = exp2f(s[j][2] - mn1);
                float p3 = exp2f(s[j][3] - mn1);
                ps0 += p0 + p1; ps1 += p2 + p3;
                uint32_t hh0 = packbf2(p0, p1), hh1 = packbf2(p2, p3);
                __nv_bfloat162 hv0 = *(__nv_bfloat162*)&hh0;
                __nv_bfloat162 hv1 = *(__nv_bfloat162*)&hh1;
                uint32_t ll0 = packbf2(p0 - __bfloat162float(hv0.x),
                                       p1 - __bfloat162float(hv0.y));
                uint32_t ll1 = packbf2(p2 - __bfloat162float(hv1.x),
                                       p3 - __bfloat162float(hv1.y));
                ap[t][q * 2]      = hh0;
                ap[t][q * 2 + 1]  = hh1;
                apl[t][q * 2]     = ll0;
                apl[t][q * 2 + 1] = ll1;
            }
        }
        ps0 += __shfl_xor_sync(0xffffffffu, ps0, 1);
        ps0 += __shfl_xor_sync(0xffffffffu, ps0, 2);
        ps1 += __shfl_xor_sync(0xffffffffu, ps1, 1);
        ps1 += __shfl_xor_sync(0xffffffffu, ps1, 2);
        l0 = l0 * sc0 + ps0;
        l1 = l1 * sc1 + ps1;
        m0 = mn0; m1 = mn1;

        #pragma unroll
        for (int f = 0; f < 16; f++) {
            acc_o[f][0] *= sc0; acc_o[f][1] *= sc0;
            acc_o[f][2] *= sc1; acc_o[f][3] *= sc1;
        }

        #pragma unroll
        for (int t = 0; t < 4; t++) {
            #pragma unroll
            for (int db = 0; db < 8; db++) {
                uint32_t bv[4];
                ldsm4t(bv, sb + VH_OFF + v_off + (uint32_t)t * (16 * ASTR) + db * 32);
                mma16816(acc_o[db * 2],     ap[t],  bv[0], bv[1]);
                mma16816(acc_o[db * 2 + 1], ap[t],  bv[2], bv[3]);
                mma16816(acc_o[db * 2],     apl[t], bv[0], bv[1]);
                mma16816(acc_o[db * 2 + 1], apl[t], bv[2], bv[3]);
                ldsm4t(bv, sb + VL_OFF + v_off + (uint32_t)t * (16 * ASTR) + db * 32);
                mma16816(acc_o[db * 2],     ap[t],  bv[0], bv[1]);
                mma16816(acc_o[db * 2 + 1], ap[t],  bv[2], bv[3]);
            }
        }
    }

    float inv0 = 1.f / l0, inv1 = 1.f / l1;
    const size_t row0 = (size_t)(b * SEQ + qrow0);
    const int col0 = h * HD + 2 * (lane & 3);
    #pragma unroll
    for (int f = 0; f < 16; f++) {
        *(float2*)(g_ctx + row0 * HID + col0 + 8 * f) =
            make_float2(acc_o[f][0] * inv0, acc_o[f][1] * inv0);
        *(float2*)(g_ctx + (row0 + 8) * HID + col0 + 8 * f) =
            make_float2(acc_o[f][2] * inv1, acc_o[f][3] * inv1);
    }
}

// ---------------------------------------------------------------------------
extern "C" void kernel_launch(void* const* d_in, const int* in_sizes, int n_in,
                              void* d_out, int out_size) {
    const float* hidden = (const float*)d_in[0];
    const float* cosb   = (const float*)d_in[1];
    const float* sinb   = (const float*)d_in[2];
    const float* wqkv   = (const float*)d_in[3];
    const float* wo     = (const float*)d_in[4];
    const float* kc_in  = (const float*)d_in[5];
    const float* vc_in  = (const float*)d_in[6];
    const int*   slots  = (const int*)d_in[7];
    float* out = (float*)d_out;

    const size_t out_elems   = (size_t)TT * HID;
    const size_t cache_elems = (size_t)NSLOTS * NKV * HD;
    float* okc = nullptr;
    float* ovc = nullptr;
    if ((size_t)out_size >= out_elems + 2 * cache_elems) {
        okc = out + out_elems;
        ovc = okc + cache_elems;
    }

    cudaFuncSetAttribute(gemm_bf16, cudaFuncAttributeMaxDynamicSharedMemorySize, GEMM_SMEM);
    cudaFuncSetAttribute(attn_mma, cudaFuncAttributeMaxDynamicSharedMemorySize, ATT_SMEM);

    if (okc) {
        int n4 = (int)(cache_elems / 4);
        copy_caches<<<(n4 + 255) / 256, 256>>>((const float4*)kc_in, (const float4*)vc_in,
                                               (float4*)okc, (float4*)ovc, n4);
    }

    // expand operands for QKV GEMM
    expand3<<<(TT   * (KTOT / 4) + 255) / 256, 256>>>(hidden, TT,   0);
    expand3<<<(QKVN * (KTOT / 4) + 255) / 256, 256>>>(wqkv,   QKVN, 1);

    // 1) QKV projection -> g_qkv
    gemm_bf16<<<dim3(QKVN / BN, TT / BM), 256, GEMM_SMEM>>>(0, nullptr);

    // 2) RoPE + k scatter
    {
        int n = TT * (NH + NKV) * ROT;
        rope_scatter<<<(n + 255) / 256, 256>>>(cosb, sinb, slots, okc);
    }
    // 3) v scatter
    if (ovc) {
        v_scatter<<<(TT * NKV * HD + 255) / 256, 256>>>(slots, ovc);
    }

    // 4) attention -> g_ctx (tensor cores)
    attn_mma<<<dim3(SEQ / 128, NH, BATCH), 256, ATT_SMEM>>>();

    // 5) expand ctx + w_o, then O projection -> d_out
    expand3<<<(TT  * (KTOT / 4) + 255) / 256, 256>>>(nullptr, TT,  3);
    expand3<<<(HID * (KTOT / 4) + 255) / 256, 256>>>(wo,      HID, 2);
    gemm_bf16<<<dim3(HID / BN, TT / BM), 256, GEMM_SMEM>>>(1, out);
}

// round 11
// speedup vs baseline: 1.3492x; 1.3492x over previous
#include <cuda_runtime.h>
#include <cuda_bf16.h>
#include <math.h>
#include <stdint.h>

#define TT     4096      // total tokens B*S
#define SEQ    1024
#define BATCH  4
#define HID    4096
#define NH     32
#define NKV    8
#define HD     128
#define QKVN   6144      // NH*HD + 2*NKV*HD
#define NSLOTS 8192
#define ROT    64
#define KTOT   4096      // logical GEMM K (= HID)
#define KP     12288     // expanded K: [seg0 | seg1 | seg2]

// ---------------------------------------------------------------------------
// Scratch (no cudaMalloc allowed)
// ---------------------------------------------------------------------------
__device__ float g_qkv[(size_t)TT * QKVN];               // fp32 qkv activations
__device__ float g_ctx[(size_t)TT * HID];                // fp32 attention context
__device__ __nv_bfloat16 g_aexp    [(size_t)TT   * KP];  // hidden  [hi|lo|hi]
__device__ __nv_bfloat16 g_wqkv_exp[(size_t)QKVN * KP];  // w_qkv   [hi|hi|lo]
__device__ __nv_bfloat16 g_wo_exp  [(size_t)HID  * KP];  // w_o     [hi|hi|lo]
__device__ __nv_bfloat16 g_ctx_exp [(size_t)TT   * KP];  // ctx     [hi|lo|hi]

// ---------------------------------------------------------------------------
// helpers
// ---------------------------------------------------------------------------
__device__ __forceinline__ uint32_t smem_u32(const void* p) {
    uint32_t a;
    asm("{ .reg .u64 t; cvta.to.shared.u64 t, %1; cvt.u32.u64 %0, t; }" : "=r"(a) : "l"(p));
    return a;
}
__device__ __forceinline__ void cp_async16(uint32_t dst, const void* src) {
    asm volatile("cp.async.cg.shared.global [%0], [%1], 16;" :: "r"(dst), "l"(src));
}
__device__ __forceinline__ void ldsm4(uint32_t* r, uint32_t addr) {
    asm volatile("ldmatrix.sync.aligned.m8n8.x4.shared.b16 {%0,%1,%2,%3}, [%4];"
        : "=r"(r[0]), "=r"(r[1]), "=r"(r[2]), "=r"(r[3]) : "r"(addr));
}
__device__ __forceinline__ void ldsm4t(uint32_t* r, uint32_t addr) {
    asm volatile("ldmatrix.sync.aligned.m8n8.x4.trans.shared.b16 {%0,%1,%2,%3}, [%4];"
        : "=r"(r[0]), "=r"(r[1]), "=r"(r[2]), "=r"(r[3]) : "r"(addr));
}
__device__ __forceinline__ void mma16816(float* c, const uint32_t* a, uint32_t b0, uint32_t b1) {
    asm volatile(
        "mma.sync.aligned.m16n8k16.row.col.f32.bf16.bf16.f32 "
        "{%0,%1,%2,%3}, {%4,%5,%6,%7}, {%8,%9}, {%0,%1,%2,%3};"
        : "+f"(c[0]), "+f"(c[1]), "+f"(c[2]), "+f"(c[3])
        : "r"(a[0]), "r"(a[1]), "r"(a[2]), "r"(a[3]), "r"(b0), "r"(b1));
}
__device__ __forceinline__ uint32_t packbf2(float lo, float hi) {
    __nv_bfloat162 v(__float2bfloat16(lo), __float2bfloat16(hi));
    return *(uint32_t*)&v;
}

// ---------------------------------------------------------------------------
// fp32 -> triple-segment bf16 expansion (GEMM operands)
// A-type rows (activations): [hi | lo | hi] ; B-type rows (weights): [hi | hi | lo]
// ---------------------------------------------------------------------------
__global__ void expand3(const float* __restrict__ src, int rows, int mode) {
    __nv_bfloat16* dst = (mode == 0) ? g_aexp : (mode == 1) ? g_wqkv_exp
                        : (mode == 2) ? g_wo_exp : g_ctx_exp;
    const float* s = (mode == 3) ? g_ctx : src;
    int idx = blockIdx.x * blockDim.x + threadIdx.x;
    int total = rows * (KTOT / 4);
    if (idx >= total) return;
    int row = idx >> 10;
    int c4  = idx & 1023;
    float4 v = *(const float4*)(s + (size_t)row * KTOT + c4 * 4);
    __nv_bfloat16 h0 = __float2bfloat16(v.x);
    __nv_bfloat16 h1 = __float2bfloat16(v.y);
    __nv_bfloat16 h2 = __float2bfloat16(v.z);
    __nv_bfloat16 h3 = __float2bfloat16(v.w);
    __nv_bfloat16 l0 = __float2bfloat16(v.x - __bfloat162float(h0));
    __nv_bfloat16 l1 = __float2bfloat16(v.y - __bfloat162float(h1));
    __nv_bfloat16 l2 = __float2bfloat16(v.z - __bfloat162float(h2));
    __nv_bfloat16 l3 = __float2bfloat16(v.w - __bfloat162float(h3));
    __nv_bfloat162 hA(h0, h1), hB(h2, h3), lA(l0, l1), lB(l2, l3);
    size_t base = (size_t)row * KP + c4 * 4;
    __nv_bfloat162* d0 = (__nv_bfloat162*)(dst + base);
    __nv_bfloat162* d1 = (__nv_bfloat162*)(dst + base + KTOT);
    __nv_bfloat162* d2 = (__nv_bfloat162*)(dst + base + 2 * KTOT);
    d0[0] = hA; d0[1] = hB;
    bool atype = (mode == 0 || mode == 3);
    if (atype) { d1[0] = lA; d1[1] = lB; d2[0] = hA; d2[1] = hB; }
    else       { d1[0] = hA; d1[1] = hB; d2[0] = lA; d2[1] = lB; }
}

// ---------------------------------------------------------------------------
// bf16 mma.sync GEMM: C[M,N] = A'[M,KP] @ B'[N,KP]^T, fp32 accumulate.
// CTA 128x128, BK=64, 3-stage cp.async pipeline, 8 warps in 4(M) x 2(N)
// -> 32x64 warp tile (regs ~126 -> 2 CTAs/SM = 16 warps).
// Halved sync count vs BK=32 (192 barriers instead of 384).
// Rows padded to 144 B -> conflict-free ldmatrix (36 banks stride mod 32 = 4).
// ---------------------------------------------------------------------------
#define BM 128
#define BN 128
#define BK 64
#define STAGES 3
#define ROWB 144                         // 64 bf16 data (128 B) + 16 B pad
#define TILEB (128 * ROWB)               // 18432
#define STAGEB (2 * TILEB)               // 36864
#define GEMM_SMEM (STAGES * STAGEB)      // 110592
#define NCH (KP / BK)                    // 192

__device__ __forceinline__ void load_stage(const __nv_bfloat16* __restrict__ A,
                                           const __nv_bfloat16* __restrict__ B,
                                           int bm, int bn, int k0,
                                           uint32_t stage_base, int tid) {
    #pragma unroll
    for (int it = 0; it < 8; it++) {
        int idx = tid + it * 256;          // 0..2047
        int tile = idx >> 10;              // 0:A 1:B
        int r = (idx >> 3) & 127;
        int c = idx & 7;
        const __nv_bfloat16* src =
            (tile ? (B + (size_t)(bn + r) * KP) : (A + (size_t)(bm + r) * KP)) + k0 + c * 8;
        uint32_t dst = stage_base + tile * TILEB + r * ROWB + c * 16;
        cp_async16(dst, src);
    }
    asm volatile("cp.async.commit_group;" ::: "memory");
}

__global__ __launch_bounds__(256, 2)
void gemm_bf16(int mode, float* __restrict__ outp) {
    extern __shared__ char smem[];
    const uint32_t sb = smem_u32(smem);
    const int tid  = threadIdx.x;
    const int wid  = tid >> 5;
    const int lane = tid & 31;
    const int wm   = wid & 3;          // 0..3, 32 rows each
    const int wn   = wid >> 2;         // 0..1, 64 cols each

    const __nv_bfloat16* A;
    const __nv_bfloat16* B;
    float* C;
    int Ntot;
    if (mode == 0) { A = g_aexp;    B = g_wqkv_exp; C = g_qkv; Ntot = QKVN; }
    else           { A = g_ctx_exp; B = g_wo_exp;   C = outp;  Ntot = HID;  }

    const int bn = blockIdx.x * BN;
    const int bm = blockIdx.y * BM;

    float acc[2][8][4];
    #pragma unroll
    for (int mi = 0; mi < 2; mi++)
        #pragma unroll
        for (int ni = 0; ni < 8; ni++)
            #pragma unroll
            for (int q = 0; q < 4; q++) acc[mi][ni][q] = 0.f;

    // LDSM per-thread base offsets (add stage base + ks*32 bytes)
    const uint32_t a_off0 = (uint32_t)(wm * 32 +      (lane & 15)) * ROWB + (lane >> 4) * 16;
    const uint32_t a_off1 = (uint32_t)(wm * 32 + 16 + (lane & 15)) * ROWB + (lane >> 4) * 16;
    const uint32_t b_off  = (uint32_t)(wn * 64 + (lane & 7) + ((lane >> 4) & 1) * 8) * ROWB
                          + ((lane >> 3) & 1) * 16;

    // prologue: stages 0 and 1
    load_stage(A, B, bm, bn, 0,  sb,          tid);
    load_stage(A, B, bm, bn, BK, sb + STAGEB, tid);

    #pragma unroll 1
    for (int i = 0; i < NCH; i++) {
        if (i < NCH - 1) asm volatile("cp.async.wait_group 1;" ::: "memory");
        else             asm volatile("cp.async.wait_group 0;" ::: "memory");
        __syncthreads();   // stage i visible; all warps done with stage i-1's buffer

        if (i + 2 < NCH) {
            int nb = (i + 2) % STAGES;     // == (i-1)%STAGES, freed by the barrier above
            load_stage(A, B, bm, bn, (i + 2) * BK, sb + nb * STAGEB, tid);
        }

        const uint32_t As = sb + (i % STAGES) * STAGEB;
        const uint32_t Bs = As + TILEB;

        #pragma unroll
        for (int ks = 0; ks < 4; ks++) {
            const uint32_t koff = ks * 32;
            uint32_t a[2][4];
            ldsm4(a[0], As + a_off0 + koff);
            ldsm4(a[1], As + a_off1 + koff);
            uint32_t b[4][4];
            #pragma unroll
            for (int p = 0; p < 4; p++)
                ldsm4(b[p], Bs + b_off + (uint32_t)p * (16 * ROWB) + koff);
            #pragma unroll
            for (int mi = 0; mi < 2; mi++)
                #pragma unroll
                for (int ni = 0; ni < 8; ni++)
                    mma16816(acc[mi][ni], a[mi],
                             b[ni >> 1][(ni & 1) * 2], b[ni >> 1][(ni & 1) * 2 + 1]);
        }
    }

    // epilogue
    const int crow = bm + wm * 32 + (lane >> 2);
    const int ccol = bn + wn * 64 + (lane & 3) * 2;
    #pragma unroll
    for (int mi = 0; mi < 2; mi++) {
        #pragma unroll
        for (int ni = 0; ni < 8; ni++) {
            float* p0 = C + (size_t)(crow + mi * 16)     * Ntot + ccol + ni * 8;
            float* p1 = C + (size_t)(crow + mi * 16 + 8) * Ntot + ccol + ni * 8;
            *(float2*)p0 = make_float2(acc[mi][ni][0], acc[mi][ni][1]);
            *(float2*)p1 = make_float2(acc[mi][ni][2], acc[mi][ni][3]);
        }
    }
}

// ---------------------------------------------------------------------------
// Cache copy + RoPE + scatters (unchanged)
// ---------------------------------------------------------------------------
__global__ void copy_caches(const float4* __restrict__ kc, const float4* __restrict__ vc,
                            float4* __restrict__ okc, float4* __restrict__ ovc, int n4) {
    int i = blockIdx.x * blockDim.x + threadIdx.x;
    if (i < n4) { okc[i] = kc[i]; ovc[i] = vc[i]; }
}

__global__ void rope_scatter(const float* __restrict__ cosb,
                             const float* __restrict__ sinb, const int* __restrict__ slots,
                             float* __restrict__ okc) {
    int idx = blockIdx.x * blockDim.x + threadIdx.x;
    if (idx >= TT * (NH + NKV) * ROT) return;
    int r    = idx & (ROT - 1);
    int head = (idx >> 6) % (NH + NKV);
    int t    = idx / (ROT * (NH + NKV));
    float c = cosb[t * ROT + r];
    float s = sinb[t * ROT + r];
    float* base = g_qkv + (size_t)t * QKVN + head * HD;
    float x1 = base[r];
    float x2 = base[r + ROT];
    float o1 = x1 * c - x2 * s;
    float o2 = x1 * s + x2 * c;
    base[r] = o1;
    base[r + ROT] = o2;
    if (head >= NH && okc != nullptr) {
        int kvh = head - NH;
        float* kcp = okc + (size_t)slots[t] * (NKV * HD) + kvh * HD;
        kcp[r] = o1;
        kcp[r + ROT] = o2;
    }
}

__global__ void v_scatter(const int* __restrict__ slots, float* __restrict__ ovc) {
    int idx = blockIdx.x * blockDim.x + threadIdx.x;
    if (idx >= TT * NKV * HD) return;
    int d   = idx & (HD - 1);
    int kvh = (idx >> 7) & (NKV - 1);
    int t   = idx >> 10;
    ovc[(size_t)slots[t] * (NKV * HD) + kvh * HD + d] =
        g_qkv[(size_t)t * QKVN + (NH + NKV) * HD + kvh * HD + d];
}

// ---------------------------------------------------------------------------
// Tensor-core flash attention (bf16 split, fp32 accumulate) — unchanged.
// ---------------------------------------------------------------------------
#define ASTR 272
#define QH_OFF 0
#define QL_OFF (128 * ASTR)
#define KH_OFF (2 * 128 * ASTR)
#define KL_OFF (KH_OFF + 64 * ASTR)
#define VH_OFF (KL_OFF + 64 * ASTR)
#define VL_OFF (VH_OFF + 64 * ASTR)
#define ATT_SMEM (VL_OFF + 64 * ASTR)

__global__ __launch_bounds__(256, 1)
void attn_mma() {
    extern __shared__ char sm[];
    const uint32_t sb = smem_u32(sm);
    const int qt  = blockIdx.x;
    const int h   = blockIdx.y;
    const int b   = blockIdx.z;
    const int kvh = h >> 2;
    const int tid  = threadIdx.x;
    const int wid  = tid >> 5;
    const int lane = tid & 31;
    const float qscale = 0.08838834764831845f * 1.4426950408889634f;

    const float* qbase = g_qkv + (size_t)(b * SEQ + qt * 128) * QKVN + h * HD;
    for (int i = tid; i < 128 * 32; i += 256) {
        int r = i >> 5, c = i & 31;
        float4 v = *(const float4*)(qbase + (size_t)r * QKVN + c * 4);
        v.x *= qscale; v.y *= qscale; v.z *= qscale; v.w *= qscale;
        __nv_bfloat16 h0 = __float2bfloat16(v.x), h1 = __float2bfloat16(v.y);
        __nv_bfloat16 h2 = __float2bfloat16(v.z), h3 = __float2bfloat16(v.w);
        __nv_bfloat16 l0 = __float2bfloat16(v.x - __bfloat162float(h0));
        __nv_bfloat16 l1 = __float2bfloat16(v.y - __bfloat162float(h1));
        __nv_bfloat16 l2 = __float2bfloat16(v.z - __bfloat162float(h2));
        __nv_bfloat16 l3 = __float2bfloat16(v.w - __bfloat162float(h3));
        __nv_bfloat162* dh = (__nv_bfloat162*)(sm + QH_OFF + r * ASTR + c * 8);
        __nv_bfloat162* dl = (__nv_bfloat162*)(sm + QL_OFF + r * ASTR + c * 8);
        dh[0] = __nv_bfloat162(h0, h1); dh[1] = __nv_bfloat162(h2, h3);
        dl[0] = __nv_bfloat162(l0, l1); dl[1] = __nv_bfloat162(l2, l3);
    }

    float acc_o[16][4];
    #pragma unroll
    for (int f = 0; f < 16; f++)
        #pragma unroll
        for (int q = 0; q < 4; q++) acc_o[f][q] = 0.f;
    float m0 = -INFINITY, m1 = -INFINITY, l0 = 0.f, l1 = 0.f;

    const float* kb0 = g_qkv + (size_t)(b * SEQ) * QKVN + NH * HD + kvh * HD;
    const float* vb0 = kb0 + NKV * HD;
    const int qrow0 = qt * 128 + 16 * wid + (lane >> 2);

    const uint32_t a_off = (uint32_t)(16 * wid + (lane & 15)) * ASTR + (lane >> 4) * 16;
    const uint32_t kb_off = (uint32_t)((lane & 7) + ((lane >> 4) & 1) * 8) * ASTR
                          + ((lane >> 3) & 1) * 16;
    const uint32_t v_off = (uint32_t)(lane & 15) * ASTR + (lane >> 4) * 16;

    const int nkt = 2 * qt + 2;
    for (int kt = 0; kt < nkt; kt++) {
        __syncthreads();
        for (int i = tid; i < 64 * 32 * 2; i += 256) {
            int ten = i >> 11;
            int r = (i >> 5) & 63, c = i & 31;
            const float* src = (ten ? vb0 : kb0) + (size_t)(kt * 64 + r) * QKVN + c * 4;
            float4 v = *(const float4*)src;
            __nv_bfloat16 h0 = __float2bfloat16(v.x), h1 = __float2bfloat16(v.y);
            __nv_bfloat16 h2 = __float2bfloat16(v.z), h3 = __float2bfloat16(v.w);
            __nv_bfloat16 e0 = __float2bfloat16(v.x - __bfloat162float(h0));
            __nv_bfloat16 e1 = __float2bfloat16(v.y - __bfloat162float(h1));
            __nv_bfloat16 e2 = __float2bfloat16(v.z - __bfloat162float(h2));
            __nv_bfloat16 e3 = __float2bfloat16(v.w - __bfloat162float(h3));
            int hof = (ten ? VH_OFF : KH_OFF) + r * ASTR + c * 8;
            int lof = (ten ? VL_OFF : KL_OFF) + r * ASTR + c * 8;
            __nv_bfloat162* dh = (__nv_bfloat162*)(sm + hof);
            __nv_bfloat162* dl = (__nv_bfloat162*)(sm + lof);
            dh[0] = __nv_bfloat162(h0, h1); dh[1] = __nv_bfloat162(h2, h3);
            dl[0] = __nv_bfloat162(e0, e1); dl[1] = __nv_bfloat162(e2, e3);
        }
        __syncthreads();

        float s[8][4];
        #pragma unroll
        for (int j = 0; j < 8; j++)
            #pragma unroll
            for (int q = 0; q < 4; q++) s[j][q] = 0.f;

        #pragma unroll
        for (int kk = 0; kk < 8; kk++) {
            uint32_t ah[4], al[4];
            ldsm4(ah, sb + QH_OFF + a_off + kk * 32);
            ldsm4(al, sb + QL_OFF + a_off + kk * 32);
            uint32_t bh[4][4], bl[4][4];
            #pragma unroll
            for (int p = 0; p < 4; p++) {
                ldsm4(bh[p], sb + KH_OFF + kb_off + (uint32_t)p * (16 * ASTR) + kk * 32);
                ldsm4(bl[p], sb + KL_OFF + kb_off + (uint32_t)p * (16 * ASTR) + kk * 32);
            }
            #pragma unroll
            for (int p = 0; p < 4; p++)
                #pragma unroll
                for (int q = 0; q < 2; q++) {
                    int j = p * 2 + q;
                    mma16816(s[j], ah, bh[p][q * 2], bh[p][q * 2 + 1]);
                    mma16816(s[j], al, bh[p][q * 2], bh[p][q * 2 + 1]);
                    mma16816(s[j], ah, bl[p][q * 2], bl[p][q * 2 + 1]);
                }
        }

        if (kt >= 2 * qt) {
            #pragma unroll
            for (int j = 0; j < 8; j++) {
                int c0 = kt * 64 + 8 * j + 2 * (lane & 3);
                if (c0     > qrow0)     s[j][0] = -INFINITY;
                if (c0 + 1 > qrow0)     s[j][1] = -INFINITY;
                if (c0     > qrow0 + 8) s[j][2] = -INFINITY;
                if (c0 + 1 > qrow0 + 8) s[j][3] = -INFINITY;
            }
        }
        float tm0 = -INFINITY, tm1 = -INFINITY;
        #pragma unroll
        for (int j = 0; j < 8; j++) {
            tm0 = fmaxf(tm0, fmaxf(s[j][0], s[j][1]));
            tm1 = fmaxf(tm1, fmaxf(s[j][2], s[j][3]));
        }
        tm0 = fmaxf(tm0, __shfl_xor_sync(0xffffffffu, tm0, 1));
        tm0 = fmaxf(tm0, __shfl_xor_sync(0xffffffffu, tm0, 2));
        tm1 = fmaxf(tm1, __shfl_xor_sync(0xffffffffu, tm1, 1));
        tm1 = fmaxf(tm1, __shfl_xor_sync(0xffffffffu, tm1, 2));
        float mn0 = fmaxf(m0, tm0), mn1 = fmaxf(m1, tm1);
        float sc0 = exp2f(m0 - mn0), sc1 = exp2f(m1 - mn1);

        uint32_t ap[4][4], apl[4][4];
        float ps0 = 0.f, ps1 = 0.f;
        #pragma unroll
        for (int t = 0; t < 4; t++) {
            #pragma unroll
            for (int q = 0; q < 2; q++) {
                int j = t * 2 + q;
                float p0 = exp2f(s[j][0] - mn0);
                float p1 = exp2f(s[j][1] - mn0);
                float p2 = exp2f(s[j][2] - mn1);
                float p3 = exp2f(s[j][3] - mn1);
                ps0 += p0 + p1; ps1 += p2 + p3;
                uint32_t hh0 = packbf2(p0, p1), hh1 = packbf2(p2, p3);
                __nv_bfloat162 hv0 = *(__nv_bfloat162*)&hh0;
                __nv_bfloat162 hv1 = *(__nv_bfloat162*)&hh1;
                uint32_t ll0 = packbf2(p0 - __bfloat162float(hv0.x),
                                       p1 - __bfloat162float(hv0.y));
                uint32_t ll1 = packbf2(p2 - __bfloat162float(hv1.x),
                                       p3 - __bfloat162float(hv1.y));
                ap[t][q * 2]      = hh0;
                ap[t][q * 2 + 1]  = hh1;
                apl[t][q * 2]     = ll0;
                apl[t][q * 2 + 1] = ll1;
            }
        }
        ps0 += __shfl_xor_sync(0xffffffffu, ps0, 1);
        ps0 += __shfl_xor_sync(0xffffffffu, ps0, 2);
        ps1 += __shfl_xor_sync(0xffffffffu, ps1, 1);
        ps1 += __shfl_xor_sync(0xffffffffu, ps1, 2);
        l0 = l0 * sc0 + ps0;
        l1 = l1 * sc1 + ps1;
        m0 = mn0; m1 = mn1;

        #pragma unroll
        for (int f = 0; f < 16; f++) {
            acc_o[f][0] *= sc0; acc_o[f][1] *= sc0;
            acc_o[f][2] *= sc1; acc_o[f][3] *= sc1;
        }

        #pragma unroll
        for (int t = 0; t < 4; t++) {
            #pragma unroll
            for (int db = 0; db < 8; db++) {
                uint32_t bv[4];
                ldsm4t(bv, sb + VH_OFF + v_off + (uint32_t)t * (16 * ASTR) + db * 32);
                mma16816(acc_o[db * 2],     ap[t],  bv[0], bv[1]);
                mma16816(acc_o[db * 2 + 1], ap[t],  bv[2], bv[3]);
                mma16816(acc_o[db * 2],     apl[t], bv[0], bv[1]);
                mma16816(acc_o[db * 2 + 1], apl[t], bv[2], bv[3]);
                ldsm4t(bv, sb + VL_OFF + v_off + (uint32_t)t * (16 * ASTR) + db * 32);
                mma16816(acc_o[db * 2],     ap[t],  bv[0], bv[1]);
                mma16816(acc_o[db * 2 + 1], ap[t],  bv[2], bv[3]);
            }
        }
    }

    float inv0 = 1.f / l0, inv1 = 1.f / l1;
    const size_t row0 = (size_t)(b * SEQ + qrow0);
    const int col0 = h * HD + 2 * (lane & 3);
    #pragma unroll
    for (int f = 0; f < 16; f++) {
        *(float2*)(g_ctx + row0 * HID + col0 + 8 * f) =
            make_float2(acc_o[f][0] * inv0, acc_o[f][1] * inv0);
        *(float2*)(g_ctx + (row0 + 8) * HID + col0 + 8 * f) =
            make_float2(acc_o[f][2] * inv1, acc_o[f][3] * inv1);
    }
}

// ---------------------------------------------------------------------------
extern "C" void kernel_launch(void* const* d_in, const int* in_sizes, int n_in,
                              void* d_out, int out_size) {
    const float* hidden = (const float*)d_in[0];
    const float* cosb   = (const float*)d_in[1];
    const float* sinb   = (const float*)d_in[2];
    const float* wqkv   = (const float*)d_in[3];
    const float* wo     = (const float*)d_in[4];
    const float* kc_in  = (const float*)d_in[5];
    const float* vc_in  = (const float*)d_in[6];
    const int*   slots  = (const int*)d_in[7];
    float* out = (float*)d_out;

    const size_t out_elems   = (size_t)TT * HID;
    const size_t cache_elems = (size_t)NSLOTS * NKV * HD;
    float* okc = nullptr;
    float* ovc = nullptr;
    if ((size_t)out_size >= out_elems + 2 * cache_elems) {
        okc = out + out_elems;
        ovc = okc + cache_elems;
    }

    cudaFuncSetAttribute(gemm_bf16, cudaFuncAttributeMaxDynamicSharedMemorySize, GEMM_SMEM);
    cudaFuncSetAttribute(attn_mma, cudaFuncAttributeMaxDynamicSharedMemorySize, ATT_SMEM);

    if (okc) {
        int n4 = (int)(cache_elems / 4);
        copy_caches<<<(n4 + 255) / 256, 256>>>((const float4*)kc_in, (const float4*)vc_in,
                                               (float4*)okc, (float4*)ovc, n4);
    }

    // expand operands for QKV GEMM
    expand3<<<(TT   * (KTOT / 4) + 255) / 256, 256>>>(hidden, TT,   0);
    expand3<<<(QKVN * (KTOT / 4) + 255) / 256, 256>>>(wqkv,   QKVN, 1);

    // 1) QKV projection -> g_qkv
    gemm_bf16<<<dim3(QKVN / BN, TT / BM), 256, GEMM_SMEM>>>(0, nullptr);

    // 2) RoPE + k scatter
    {
        int n = TT * (NH + NKV) * ROT;
        rope_scatter<<<(n + 255) / 256, 256>>>(cosb, sinb, slots, okc);
    }
    // 3) v scatter
    if (ovc) {
        v_scatter<<<(TT * NKV * HD + 255) / 256, 256>>>(slots, ovc);
    }

    // 4) attention -> g_ctx (tensor cores)
    attn_mma<<<dim3(SEQ / 128, NH, BATCH), 256, ATT_SMEM>>>();

    // 5) expand ctx + w_o, then O projection -> d_out
    expand3<<<(TT  * (KTOT / 4) + 255) / 256, 256>>>(nullptr, TT,  3);
    expand3<<<(HID * (KTOT / 4) + 255) / 256, 256>>>(wo,      HID, 2);
    gemm_bf16<<<dim3(HID / BN, TT / BM), 256, GEMM_SMEM>>>(1, out);
}

// round 13
// speedup vs baseline: 1.8927x; 1.4028x over previous
#include <cuda_runtime.h>
#include <cuda_bf16.h>
#include <cuda_fp16.h>
#include <math.h>
#include <stdint.h>

#define TT     4096      // total tokens B*S
#define SEQ    1024
#define BATCH  4
#define HID    4096
#define NH     32
#define NKV    8
#define HD     128
#define QKVN   6144      // NH*HD + 2*NKV*HD
#define NSLOTS 8192
#define ROT    64
#define KTOT   4096      // logical GEMM K (= HID)
#define KPA    8192      // expanded A row: [hi | lo] fp16

// ---------------------------------------------------------------------------
// Scratch (no cudaMalloc allowed)
// ---------------------------------------------------------------------------
__device__ float g_qkv[(size_t)TT * QKVN];              // fp32 qkv activations
__device__ float g_ctx[(size_t)TT * HID];               // fp32 attention context
__device__ __half g_aexp    [(size_t)TT   * KPA];       // hidden*32  [hi|lo]
__device__ __half g_ctx_exp [(size_t)TT   * KPA];       // ctx*32     [hi|lo]
__device__ __half g_wqkv_exp[(size_t)QKVN * KTOT];      // w_qkv*32   [hi]
__device__ __half g_wo_exp  [(size_t)HID  * KTOT];      // w_o*32     [hi]

// ---------------------------------------------------------------------------
// helpers
// ---------------------------------------------------------------------------
__device__ __forceinline__ uint32_t smem_u32(const void* p) {
    uint32_t a;
    asm("{ .reg .u64 t; cvta.to.shared.u64 t, %1; cvt.u32.u64 %0, t; }" : "=r"(a) : "l"(p));
    return a;
}
__device__ __forceinline__ void cp_async16(uint32_t dst, const void* src) {
    asm volatile("cp.async.cg.shared.global [%0], [%1], 16;" :: "r"(dst), "l"(src));
}
__device__ __forceinline__ void ldsm4(uint32_t* r, uint32_t addr) {
    asm volatile("ldmatrix.sync.aligned.m8n8.x4.shared.b16 {%0,%1,%2,%3}, [%4];"
        : "=r"(r[0]), "=r"(r[1]), "=r"(r[2]), "=r"(r[3]) : "r"(addr));
}
__device__ __forceinline__ void ldsm4t(uint32_t* r, uint32_t addr) {
    asm volatile("ldmatrix.sync.aligned.m8n8.x4.trans.shared.b16 {%0,%1,%2,%3}, [%4];"
        : "=r"(r[0]), "=r"(r[1]), "=r"(r[2]), "=r"(r[3]) : "r"(addr));
}
// bf16 mma (attention)
__device__ __forceinline__ void mma16816(float* c, const uint32_t* a, uint32_t b0, uint32_t b1) {
    asm volatile(
        "mma.sync.aligned.m16n8k16.row.col.f32.bf16.bf16.f32 "
        "{%0,%1,%2,%3}, {%4,%5,%6,%7}, {%8,%9}, {%0,%1,%2,%3};"
        : "+f"(c[0]), "+f"(c[1]), "+f"(c[2]), "+f"(c[3])
        : "r"(a[0]), "r"(a[1]), "r"(a[2]), "r"(a[3]), "r"(b0), "r"(b1));
}
// fp16 mma (projection GEMMs)
__device__ __forceinline__ void mma16816h(float* c, const uint32_t* a, uint32_t b0, uint32_t b1) {
    asm volatile(
        "mma.sync.aligned.m16n8k16.row.col.f32.f16.f16.f32 "
        "{%0,%1,%2,%3}, {%4,%5,%6,%7}, {%8,%9}, {%0,%1,%2,%3};"
        : "+f"(c[0]), "+f"(c[1]), "+f"(c[2]), "+f"(c[3])
        : "r"(a[0]), "r"(a[1]), "r"(a[2]), "r"(a[3]), "r"(b0), "r"(b1));
}
__device__ __forceinline__ uint32_t packbf2(float lo, float hi) {
    __nv_bfloat162 v(__float2bfloat16(lo), __float2bfloat16(hi));
    return *(uint32_t*)&v;
}

// ---------------------------------------------------------------------------
// fp32 -> fp16 split expansion (scaled by 32)
// A-type (activations): [hi | lo] rows of KPA.  B-type (weights): [hi] rows of KTOT.
// mode: 0 hidden->g_aexp(A), 1 wqkv->g_wqkv_exp(B), 2 wo->g_wo_exp(B),
//       3 g_ctx->g_ctx_exp(A)
// ---------------------------------------------------------------------------
__global__ void expand2(const float* __restrict__ src, int rows, int mode) {
    int idx = blockIdx.x * blockDim.x + threadIdx.x;
    int total = rows * (KTOT / 4);
    if (idx >= total) return;
    int row = idx >> 10;
    int c4  = idx & 1023;
    const float* s = (mode == 3) ? g_ctx : src;
    float4 v = *(const float4*)(s + (size_t)row * KTOT + c4 * 4);
    const float sc = 32.0f;
    float a0 = v.x * sc, a1 = v.y * sc, a2 = v.z * sc, a3 = v.w * sc;
    __half h0 = __float2half_rn(a0), h1 = __float2half_rn(a1);
    __half h2 = __float2half_rn(a2), h3 = __float2half_rn(a3);
    if (mode == 0 || mode == 3) {
        __half* dst = (mode == 0) ? g_aexp : g_ctx_exp;
        __half l0 = __float2half_rn(a0 - __half2float(h0));
        __half l1 = __float2half_rn(a1 - __half2float(h1));
        __half l2 = __float2half_rn(a2 - __half2float(h2));
        __half l3 = __float2half_rn(a3 - __half2float(h3));
        size_t base = (size_t)row * KPA + c4 * 4;
        __half2* dh = (__half2*)(dst + base);
        __half2* dl = (__half2*)(dst + base + KTOT);
        dh[0] = __half2(h0, h1); dh[1] = __half2(h2, h3);
        dl[0] = __half2(l0, l1); dl[1] = __half2(l2, l3);
    } else {
        __half* dst = (mode == 1) ? g_wqkv_exp : g_wo_exp;
        size_t base = (size_t)row * KTOT + c4 * 4;
        __half2* dh = (__half2*)(dst + base);
        dh[0] = __half2(h0, h1); dh[1] = __half2(h2, h3);
    }
}

// ---------------------------------------------------------------------------
// fp16 mma.sync GEMM: C[M,N] = (1/1024) * A'[M,KPA] @ B'[N,KTOT ring]^T.
// A' = [hi|lo] of 32*A ; B' = hi of 32*B, read twice via k mod KTOT.
// CTA 128x128, BK=64, 3-stage cp.async pipeline, 8 warps 4(M)x2(N) -> 32x64.
// Rows padded to 144 B -> conflict-free ldmatrix.
// ---------------------------------------------------------------------------
#define BM 128
#define BN 128
#define BK 64
#define STAGES 3
#define ROWB 144                         // 64 fp16 data (128 B) + 16 B pad
#define TILEB (128 * ROWB)               // 18432
#define STAGEB (2 * TILEB)               // 36864
#define GEMM_SMEM (STAGES * STAGEB)      // 110592
#define NCH (KPA / BK)                   // 128

__device__ __forceinline__ void load_stage(const __half* __restrict__ A,
                                           const __half* __restrict__ B,
                                           int bm, int bn, int k0,
                                           uint32_t stage_base, int tid) {
    const int kb = k0 & (KTOT - 1);        // B ring: reuse hi segment
    #pragma unroll
    for (int it = 0; it < 8; it++) {
        int idx = tid + it * 256;          // 0..2047
        int tile = idx >> 10;              // 0:A 1:B
        int r = (idx >> 3) & 127;
        int c = idx & 7;
        const __half* src =
            tile ? (B + (size_t)(bn + r) * KTOT + kb + c * 8)
                 : (A + (size_t)(bm + r) * KPA  + k0 + c * 8);
        uint32_t dst = stage_base + tile * TILEB + r * ROWB + c * 16;
        cp_async16(dst, src);
    }
    asm volatile("cp.async.commit_group;" ::: "memory");
}

__global__ __launch_bounds__(256, 2)
void gemm_fp16(int mode, float* __restrict__ outp) {
    extern __shared__ char smem[];
    const uint32_t sb = smem_u32(smem);
    const int tid  = threadIdx.x;
    const int wid  = tid >> 5;
    const int lane = tid & 31;
    const int wm   = wid & 3;          // 0..3, 32 rows each
    const int wn   = wid >> 2;         // 0..1, 64 cols each

    const __half* A;
    const __half* B;
    float* C;
    int Ntot;
    if (mode == 0) { A = g_aexp;    B = g_wqkv_exp; C = g_qkv; Ntot = QKVN; }
    else           { A = g_ctx_exp; B = g_wo_exp;   C = outp;  Ntot = HID;  }

    const int bn = blockIdx.x * BN;
    const int bm = blockIdx.y * BM;

    float acc[2][8][4];
    #pragma unroll
    for (int mi = 0; mi < 2; mi++)
        #pragma unroll
        for (int ni = 0; ni < 8; ni++)
            #pragma unroll
            for (int q = 0; q < 4; q++) acc[mi][ni][q] = 0.f;

    const uint32_t a_off0 = (uint32_t)(wm * 32 +      (lane & 15)) * ROWB + (lane >> 4) * 16;
    const uint32_t a_off1 = (uint32_t)(wm * 32 + 16 + (lane & 15)) * ROWB + (lane >> 4) * 16;
    const uint32_t b_off  = (uint32_t)(wn * 64 + (lane & 7) + ((lane >> 4) & 1) * 8) * ROWB
                          + ((lane >> 3) & 1) * 16;

    // prologue: stages 0 and 1
    load_stage(A, B, bm, bn, 0,  sb,          tid);
    load_stage(A, B, bm, bn, BK, sb + STAGEB, tid);

    #pragma unroll 1
    for (int i = 0; i < NCH; i++) {
        if (i < NCH - 1) asm volatile("cp.async.wait_group 1;" ::: "memory");
        else             asm volatile("cp.async.wait_group 0;" ::: "memory");
        __syncthreads();

        if (i + 2 < NCH) {
            int nb = (i + 2) % STAGES;
            load_stage(A, B, bm, bn, (i + 2) * BK, sb + nb * STAGEB, tid);
        }

        const uint32_t As = sb + (i % STAGES) * STAGEB;
        const uint32_t Bs = As + TILEB;

        #pragma unroll
        for (int ks = 0; ks < 4; ks++) {
            const uint32_t koff = ks * 32;
            uint32_t a[2][4];
            ldsm4(a[0], As + a_off0 + koff);
            ldsm4(a[1], As + a_off1 + koff);
            uint32_t b[4][4];
            #pragma unroll
            for (int p = 0; p < 4; p++)
                ldsm4(b[p], Bs + b_off + (uint32_t)p * (16 * ROWB) + koff);
            #pragma unroll
            for (int mi = 0; mi < 2; mi++)
                #pragma unroll
                for (int ni = 0; ni < 8; ni++)
                    mma16816h(acc[mi][ni], a[mi],
                              b[ni >> 1][(ni & 1) * 2], b[ni >> 1][(ni & 1) * 2 + 1]);
        }
    }

    // epilogue (unscale 32*32)
    const float inv = 1.0f / 1024.0f;
    const int crow = bm + wm * 32 + (lane >> 2);
    const int ccol = bn + wn * 64 + (lane & 3) * 2;
    #pragma unroll
    for (int mi = 0; mi < 2; mi++) {
        #pragma unroll
        for (int ni = 0; ni < 8; ni++) {
            float* p0 = C + (size_t)(crow + mi * 16)     * Ntot + ccol + ni * 8;
            float* p1 = C + (size_t)(crow + mi * 16 + 8) * Ntot + ccol + ni * 8;
            *(float2*)p0 = make_float2(acc[mi][ni][0] * inv, acc[mi][ni][1] * inv);
            *(float2*)p1 = make_float2(acc[mi][ni][2] * inv, acc[mi][ni][3] * inv);
        }
    }
}

// ---------------------------------------------------------------------------
// Cache copy + RoPE + scatters (unchanged)
// ---------------------------------------------------------------------------
__global__ void copy_caches(const float4* __restrict__ kc, const float4* __restrict__ vc,
                            float4* __restrict__ okc, float4* __restrict__ ovc, int n4) {
    int i = blockIdx.x * blockDim.x + threadIdx.x;
    if (i < n4) { okc[i] = kc[i]; ovc[i] = vc[i]; }
}

__global__ void rope_scatter(const float* __restrict__ cosb,
                             const float* __restrict__ sinb, const int* __restrict__ slots,
                             float* __restrict__ okc) {
    int idx = blockIdx.x * blockDim.x + threadIdx.x;
    if (idx >= TT * (NH + NKV) * ROT) return;
    int r    = idx & (ROT - 1);
    int head = (idx >> 6) % (NH + NKV);
    int t    = idx / (ROT * (NH + NKV));
    float c = cosb[t * ROT + r];
    float s = sinb[t * ROT + r];
    float* base = g_qkv + (size_t)t * QKVN + head * HD;
    float x1 = base[r];
    float x2 = base[r + ROT];
    float o1 = x1 * c - x2 * s;
    float o2 = x1 * s + x2 * c;
    base[r] = o1;
    base[r + ROT] = o2;
    if (head >= NH && okc != nullptr) {
        int kvh = head - NH;
        float* kcp = okc + (size_t)slots[t] * (NKV * HD) + kvh * HD;
        kcp[r] = o1;
        kcp[r + ROT] = o2;
    }
}

__global__ void v_scatter(const int* __restrict__ slots, float* __restrict__ ovc) {
    int idx = blockIdx.x * blockDim.x + threadIdx.x;
    if (idx >= TT * NKV * HD) return;
    int d   = idx & (HD - 1);
    int kvh = (idx >> 7) & (NKV - 1);
    int t   = idx >> 10;
    ovc[(size_t)slots[t] * (NKV * HD) + kvh * HD + d] =
        g_qkv[(size_t)t * QKVN + (NH + NKV) * HD + kvh * HD + d];
}

// ---------------------------------------------------------------------------
// Tensor-core flash attention (bf16 split, fp32 accumulate) — unchanged.
// ---------------------------------------------------------------------------
#define ASTR 272
#define QH_OFF 0
#define QL_OFF (128 * ASTR)
#define KH_OFF (2 * 128 * ASTR)
#define KL_OFF (KH_OFF + 64 * ASTR)
#define VH_OFF (KL_OFF + 64 * ASTR)
#define VL_OFF (VH_OFF + 64 * ASTR)
#define ATT_SMEM (VL_OFF + 64 * ASTR)

__global__ __launch_bounds__(256, 1)
void attn_mma() {
    extern __shared__ char sm[];
    const uint32_t sb = smem_u32(sm);
    const int qt  = blockIdx.x;
    const int h   = blockIdx.y;
    const int b   = blockIdx.z;
    const int kvh = h >> 2;
    const int tid  = threadIdx.x;
    const int wid  = tid >> 5;
    const int lane = tid & 31;
    const float qscale = 0.08838834764831845f * 1.4426950408889634f;

    const float* qbase = g_qkv + (size_t)(b * SEQ + qt * 128) * QKVN + h * HD;
    for (int i = tid; i < 128 * 32; i += 256) {
        int r = i >> 5, c = i & 31;
        float4 v = *(const float4*)(qbase + (size_t)r * QKVN + c * 4);
        v.x *= qscale; v.y *= qscale; v.z *= qscale; v.w *= qscale;
        __nv_bfloat16 h0 = __float2bfloat16(v.x), h1 = __float2bfloat16(v.y);
        __nv_bfloat16 h2 = __float2bfloat16(v.z), h3 = __float2bfloat16(v.w);
        __nv_bfloat16 l0 = __float2bfloat16(v.x - __bfloat162float(h0));
        __nv_bfloat16 l1 = __float2bfloat16(v.y - __bfloat162float(h1));
        __nv_bfloat16 l2 = __float2bfloat16(v.z - __bfloat162float(h2));
        __nv_bfloat16 l3 = __float2bfloat16(v.w - __bfloat162float(h3));
        __nv_bfloat162* dh = (__nv_bfloat162*)(sm + QH_OFF + r * ASTR + c * 8);
        __nv_bfloat162* dl = (__nv_bfloat162*)(sm + QL_OFF + r * ASTR + c * 8);
        dh[0] = __nv_bfloat162(h0, h1); dh[1] = __nv_bfloat162(h2, h3);
        dl[0] = __nv_bfloat162(l0, l1); dl[1] = __nv_bfloat162(l2, l3);
    }

    float acc_o[16][4];
    #pragma unroll
    for (int f = 0; f < 16; f++)
        #pragma unroll
        for (int q = 0; q < 4; q++) acc_o[f][q] = 0.f;
    float m0 = -INFINITY, m1 = -INFINITY, l0 = 0.f, l1 = 0.f;

    const float* kb0 = g_qkv + (size_t)(b * SEQ) * QKVN + NH * HD + kvh * HD;
    const float* vb0 = kb0 + NKV * HD;
    const int qrow0 = qt * 128 + 16 * wid + (lane >> 2);

    const uint32_t a_off = (uint32_t)(16 * wid + (lane & 15)) * ASTR + (lane >> 4) * 16;
    const uint32_t kb_off = (uint32_t)((lane & 7) + ((lane >> 4) & 1) * 8) * ASTR
                          + ((lane >> 3) & 1) * 16;
    const uint32_t v_off = (uint32_t)(lane & 15) * ASTR + (lane >> 4) * 16;

    const int nkt = 2 * qt + 2;
    for (int kt = 0; kt < nkt; kt++) {
        __syncthreads();
        for (int i = tid; i < 64 * 32 * 2; i += 256) {
            int ten = i >> 11;
            int r = (i >> 5) & 63, c = i & 31;
            const float* src = (ten ? vb0 : kb0) + (size_t)(kt * 64 + r) * QKVN + c * 4;
            float4 v = *(const float4*)src;
            __nv_bfloat16 h0 = __float2bfloat16(v.x), h1 = __float2bfloat16(v.y);
            __nv_bfloat16 h2 = __float2bfloat16(v.z), h3 = __float2bfloat16(v.w);
            __nv_bfloat16 e0 = __float2bfloat16(v.x - __bfloat162float(h0));
            __nv_bfloat16 e1 = __float2bfloat16(v.y - __bfloat162float(h1));
            __nv_bfloat16 e2 = __float2bfloat16(v.z - __bfloat162float(h2));
            __nv_bfloat16 e3 = __float2bfloat16(v.w - __bfloat162float(h3));
            int hof = (ten ? VH_OFF : KH_OFF) + r * ASTR + c * 8;
            int lof = (ten ? VL_OFF : KL_OFF) + r * ASTR + c * 8;
            __nv_bfloat162* dh = (__nv_bfloat162*)(sm + hof);
            __nv_bfloat162* dl = (__nv_bfloat162*)(sm + lof);
            dh[0] = __nv_bfloat162(h0, h1); dh[1] = __nv_bfloat162(h2, h3);
            dl[0] = __nv_bfloat162(e0, e1); dl[1] = __nv_bfloat162(e2, e3);
        }
        __syncthreads();

        float s[8][4];
        #pragma unroll
        for (int j = 0; j < 8; j++)
            #pragma unroll
            for (int q = 0; q < 4; q++) s[j][q] = 0.f;

        #pragma unroll
        for (int kk = 0; kk < 8; kk++) {
            uint32_t ah[4], al[4];
            ldsm4(ah, sb + QH_OFF + a_off + kk * 32);
            ldsm4(al, sb + QL_OFF + a_off + kk * 32);
            uint32_t bh[4][4], bl[4][4];
            #pragma unroll
            for (int p = 0; p < 4; p++) {
                ldsm4(bh[p], sb + KH_OFF + kb_off + (uint32_t)p * (16 * ASTR) + kk * 32);
                ldsm4(bl[p], sb + KL_OFF + kb_off + (uint32_t)p * (16 * ASTR) + kk * 32);
            }
            #pragma unroll
            for (int p = 0; p < 4; p++)
                #pragma unroll
                for (int q = 0; q < 2; q++) {
                    int j = p * 2 + q;
                    mma16816(s[j], ah, bh[p][q * 2], bh[p][q * 2 + 1]);
                    mma16816(s[j], al, bh[p][q * 2], bh[p][q * 2 + 1]);
                    mma16816(s[j], ah, bl[p][q * 2], bl[p][q * 2 + 1]);
                }
        }

        if (kt >= 2 * qt) {
            #pragma unroll
            for (int j = 0; j < 8; j++) {
                int c0 = kt * 64 + 8 * j + 2 * (lane & 3);
                if (c0     > qrow0)     s[j][0] = -INFINITY;
                if (c0 + 1 > qrow0)     s[j][1] = -INFINITY;
                if (c0     > qrow0 + 8) s[j][2] = -INFINITY;
                if (c0 + 1 > qrow0 + 8) s[j][3] = -INFINITY;
            }
        }
        float tm0 = -INFINITY, tm1 = -INFINITY;
        #pragma unroll
        for (int j = 0; j < 8; j++) {
            tm0 = fmaxf(tm0, fmaxf(s[j][0], s[j][1]));
            tm1 = fmaxf(tm1, fmaxf(s[j][2], s[j][3]));
        }
        tm0 = fmaxf(tm0, __shfl_xor_sync(0xffffffffu, tm0, 1));
        tm0 = fmaxf(tm0, __shfl_xor_sync(0xffffffffu, tm0, 2));
        tm1 = fmaxf(tm1, __shfl_xor_sync(0xffffffffu, tm1, 1));
        tm1 = fmaxf(tm1, __shfl_xor_sync(0xffffffffu, tm1, 2));
        float mn0 = fmaxf(m0, tm0), mn1 = fmaxf(m1, tm1);
        float sc0 = exp2f(m0 - mn0), sc1 = exp2f(m1 - mn1);

        uint32_t ap[4][4], apl[4][4];
        float ps0 = 0.f, ps1 = 0.f;
        #pragma unroll
        for (int t = 0; t < 4; t++) {
            #pragma unroll
            for (int q = 0; q < 2; q++) {
                int j = t * 2 + q;
                float p0 = exp2f(s[j][0] - mn0);
                float p1 = exp2f(s[j][1] - mn0);
                float p2 = exp2f(s[j][2] - mn1);
                float p3 = exp2f(s[j][3] - mn1);
                ps0 += p0 + p1; ps1 += p2 + p3;
                uint32_t hh0 = packbf2(p0, p1), hh1 = packbf2(p2, p3);
                __nv_bfloat162 hv0 = *(__nv_bfloat162*)&hh0;
                __nv_bfloat162 hv1 = *(__nv_bfloat162*)&hh1;
                uint32_t ll0 = packbf2(p0 - __bfloat162float(hv0.x),
                                       p1 - __bfloat162float(hv0.y));
                uint32_t ll1 = packbf2(p2 - __bfloat162float(hv1.x),
                                       p3 - __bfloat162float(hv1.y));
                ap[t][q * 2]      = hh0;
                ap[t][q * 2 + 1]  = hh1;
                apl[t][q * 2]     = ll0;
                apl[t][q * 2 + 1] = ll1;
            }
        }
        ps0 += __shfl_xor_sync(0xffffffffu, ps0, 1);
        ps0 += __shfl_xor_sync(0xffffffffu, ps0, 2);
        ps1 += __shfl_xor_sync(0xffffffffu, ps1, 1);
        ps1 += __shfl_xor_sync(0xffffffffu, ps1, 2);
        l0 = l0 * sc0 + ps0;
        l1 = l1 * sc1 + ps1;
        m0 = mn0; m1 = mn1;

        #pragma unroll
        for (int f = 0; f < 16; f++) {
            acc_o[f][0] *= sc0; acc_o[f][1] *= sc0;
            acc_o[f][2] *= sc1; acc_o[f][3] *= sc1;
        }

        #pragma unroll
        for (int t = 0; t < 4; t++) {
            #pragma unroll
            for (int db = 0; db < 8; db++) {
                uint32_t bv[4];
                ldsm4t(bv, sb + VH_OFF + v_off + (uint32_t)t * (16 * ASTR) + db * 32);
                mma16816(acc_o[db * 2],     ap[t],  bv[0], bv[1]);
                mma16816(acc_o[db * 2 + 1], ap[t],  bv[2], bv[3]);
                mma16816(acc_o[db * 2],     apl[t], bv[0], bv[1]);
                mma16816(acc_o[db * 2 + 1], apl[t], bv[2], bv[3]);
                ldsm4t(bv, sb + VL_OFF + v_off + (uint32_t)t * (16 * ASTR) + db * 32);
                mma16816(acc_o[db * 2],     ap[t],  bv[0], bv[1]);
                mma16816(acc_o[db * 2 + 1], ap[t],  bv[2], bv[3]);
            }
        }
    }

    float inv0 = 1.f / l0, inv1 = 1.f / l1;
    const size_t row0 = (size_t)(b * SEQ + qrow0);
    const int col0 = h * HD + 2 * (lane & 3);
    #pragma unroll
    for (int f = 0; f < 16; f++) {
        *(float2*)(g_ctx + row0 * HID + col0 + 8 * f) =
            make_float2(acc_o[f][0] * inv0, acc_o[f][1] * inv0);
        *(float2*)(g_ctx + (row0 + 8) * HID + col0 + 8 * f) =
            make_float2(acc_o[f][2] * inv1, acc_o[f][3] * inv1);
    }
}

// ---------------------------------------------------------------------------
extern "C" void kernel_launch(void* const* d_in, const int* in_sizes, int n_in,
                              void* d_out, int out_size) {
    const float* hidden = (const float*)d_in[0];
    const float* cosb   = (const float*)d_in[1];
    const float* sinb   = (const float*)d_in[2];
    const float* wqkv   = (const float*)d_in[3];
    const float* wo     = (const float*)d_in[4];
    const float* kc_in  = (const float*)d_in[5];
    const float* vc_in  = (const float*)d_in[6];
    const int*   slots  = (const int*)d_in[7];
    float* out = (float*)d_out;

    const size_t out_elems   = (size_t)TT * HID;
    const size_t cache_elems = (size_t)NSLOTS * NKV * HD;
    float* okc = nullptr;
    float* ovc = nullptr;
    if ((size_t)out_size >= out_elems + 2 * cache_elems) {
        okc = out + out_elems;
        ovc = okc + cache_elems;
    }

    cudaFuncSetAttribute(gemm_fp16, cudaFuncAttributeMaxDynamicSharedMemorySize, GEMM_SMEM);
    cudaFuncSetAttribute(attn_mma, cudaFuncAttributeMaxDynamicSharedMemorySize, ATT_SMEM);

    if (okc) {
        int n4 = (int)(cache_elems / 4);
        copy_caches<<<(n4 + 255) / 256, 256>>>((const float4*)kc_in, (const float4*)vc_in,
                                               (float4*)okc, (float4*)ovc, n4);
    }

    // expand operands for QKV GEMM
    expand2<<<(TT   * (KTOT / 4) + 255) / 256, 256>>>(hidden, TT,   0);
    expand2<<<(QKVN * (KTOT / 4) + 255) / 256, 256>>>(wqkv,   QKVN, 1);

    // 1) QKV projection -> g_qkv
    gemm_fp16<<<dim3(QKVN / BN, TT / BM), 256, GEMM_SMEM>>>(0, nullptr);

    // 2) RoPE + k scatter
    {
        int n = TT * (NH + NKV) * ROT;
        rope_scatter<<<(n + 255) / 256, 256>>>(cosb, sinb, slots, okc);
    }
    // 3) v scatter
    if (ovc) {
        v_scatter<<<(TT * NKV * HD + 255) / 256, 256>>>(slots, ovc);
    }

    // 4) attention -> g_ctx (tensor cores)
    attn_mma<<<dim3(SEQ / 128, NH, BATCH), 256, ATT_SMEM>>>();

    // 5) expand ctx + w_o, then O projection -> d_out
    expand2<<<(TT  * (KTOT / 4) + 255) / 256, 256>>>(nullptr, TT,  3);
    expand2<<<(HID * (KTOT / 4) + 255) / 256, 256>>>(wo,      HID, 2);
    gemm_fp16<<<dim3(HID / BN, TT / BM), 256, GEMM_SMEM>>>(1, out);
}

// round 16
// speedup vs baseline: 2.0475x; 1.0818x over previous
#include <cuda_runtime.h>
#include <cuda_bf16.h>
#include <cuda_fp16.h>
#include <math.h>
#include <stdint.h>

#define TT     4096      // total tokens B*S
#define SEQ    1024
#define BATCH  4
#define HID    4096
#define NH     32
#define NKV    8
#define HD     128
#define QKVN   6144      // NH*HD + 2*NKV*HD
#define NSLOTS 8192
#define ROT    64
#define KTOT   4096      // logical GEMM K (= HID)
#define KPA    8192      // expanded A row: [hi | lo] fp16

// ---------------------------------------------------------------------------
// Scratch (no cudaMalloc allowed)
// ---------------------------------------------------------------------------
__device__ float g_qkv[(size_t)TT * QKVN];              // fp32 qkv activations
__device__ __half g_aexp    [(size_t)TT   * KPA];       // hidden*32  [hi|lo]
__device__ __half g_ctx_exp [(size_t)TT   * KPA];       // ctx*32     [hi|lo] (written by attn)
__device__ __half g_wqkv_exp[(size_t)QKVN * KTOT];      // w_qkv*32   [hi]
__device__ __half g_wo_exp  [(size_t)HID  * KTOT];      // w_o*32     [hi]

// ---------------------------------------------------------------------------
// helpers
// ---------------------------------------------------------------------------
__device__ __forceinline__ uint32_t smem_u32(const void* p) {
    uint32_t a;
    asm("{ .reg .u64 t; cvta.to.shared.u64 t, %1; cvt.u32.u64 %0, t; }" : "=r"(a) : "l"(p));
    return a;
}
__device__ __forceinline__ void cp_async16(uint32_t dst, const void* src) {
    asm volatile("cp.async.cg.shared.global [%0], [%1], 16;" :: "r"(dst), "l"(src));
}
__device__ __forceinline__ void ldsm4(uint32_t* r, uint32_t addr) {
    asm volatile("ldmatrix.sync.aligned.m8n8.x4.shared.b16 {%0,%1,%2,%3}, [%4];"
        : "=r"(r[0]), "=r"(r[1]), "=r"(r[2]), "=r"(r[3]) : "r"(addr));
}
__device__ __forceinline__ void ldsm4t(uint32_t* r, uint32_t addr) {
    asm volatile("ldmatrix.sync.aligned.m8n8.x4.trans.shared.b16 {%0,%1,%2,%3}, [%4];"
        : "=r"(r[0]), "=r"(r[1]), "=r"(r[2]), "=r"(r[3]) : "r"(addr));
}
// fp16 mma
__device__ __forceinline__ void mma16816h(float* c, const uint32_t* a, uint32_t b0, uint32_t b1) {
    asm volatile(
        "mma.sync.aligned.m16n8k16.row.col.f32.f16.f16.f32 "
        "{%0,%1,%2,%3}, {%4,%5,%6,%7}, {%8,%9}, {%0,%1,%2,%3};"
        : "+f"(c[0]), "+f"(c[1]), "+f"(c[2]), "+f"(c[3])
        : "r"(a[0]), "r"(a[1]), "r"(a[2]), "r"(a[3]), "r"(b0), "r"(b1));
}
__device__ __forceinline__ uint32_t packh2(float lo, float hi) {
    __half2 v(__float2half_rn(lo), __float2half_rn(hi));
    return *(uint32_t*)&v;
}

// ---------------------------------------------------------------------------
// fp32 -> fp16 split expansion (scaled by 32)
// mode: 0 hidden->g_aexp (A-type: [hi|lo]), 1 wqkv->g_wqkv_exp (B: [hi]),
//       2 wo->g_wo_exp (B: [hi])
// ---------------------------------------------------------------------------
__global__ void expand2(const float* __restrict__ src, int rows, int mode) {
    int idx = blockIdx.x * blockDim.x + threadIdx.x;
    int total = rows * (KTOT / 4);
    if (idx >= total) return;
    int row = idx >> 10;
    int c4  = idx & 1023;
    float4 v = *(const float4*)(src + (size_t)row * KTOT + c4 * 4);
    const float sc = 32.0f;
    float a0 = v.x * sc, a1 = v.y * sc, a2 = v.z * sc, a3 = v.w * sc;
    __half h0 = __float2half_rn(a0), h1 = __float2half_rn(a1);
    __half h2 = __float2half_rn(a2), h3 = __float2half_rn(a3);
    if (mode == 0) {
        __half l0 = __float2half_rn(a0 - __half2float(h0));
        __half l1 = __float2half_rn(a1 - __half2float(h1));
        __half l2 = __float2half_rn(a2 - __half2float(h2));
        __half l3 = __float2half_rn(a3 - __half2float(h3));
        size_t base = (size_t)row * KPA + c4 * 4;
        __half2* dh = (__half2*)(g_aexp + base);
        __half2* dl = (__half2*)(g_aexp + base + KTOT);
        dh[0] = __half2(h0, h1); dh[1] = __half2(h2, h3);
        dl[0] = __half2(l0, l1); dl[1] = __half2(l2, l3);
    } else {
        __half* dst = (mode == 1) ? g_wqkv_exp : g_wo_exp;
        size_t base = (size_t)row * KTOT + c4 * 4;
        __half2* dh = (__half2*)(dst + base);
        dh[0] = __half2(h0, h1); dh[1] = __half2(h2, h3);
    }
}

// ---------------------------------------------------------------------------
// fp16 mma.sync GEMM (unchanged from round 13): C = (1/1024) A'[M,KPA] B'^T
// ---------------------------------------------------------------------------
#define BM 128
#define BN 128
#define BK 64
#define STAGES 3
#define ROWB 144
#define TILEB (128 * ROWB)
#define STAGEB (2 * TILEB)
#define GEMM_SMEM (STAGES * STAGEB)
#define NCH (KPA / BK)

__device__ __forceinline__ void load_stage(const __half* __restrict__ A,
                                           const __half* __restrict__ B,
                                           int bm, int bn, int k0,
                                           uint32_t stage_base, int tid) {
    const int kb = k0 & (KTOT - 1);        // B ring: reuse hi segment
    #pragma unroll
    for (int it = 0; it < 8; it++) {
        int idx = tid + it * 256;
        int tile = idx >> 10;
        int r = (idx >> 3) & 127;
        int c = idx & 7;
        const __half* src =
            tile ? (B + (size_t)(bn + r) * KTOT + kb + c * 8)
                 : (A + (size_t)(bm + r) * KPA  + k0 + c * 8);
        uint32_t dst = stage_base + tile * TILEB + r * ROWB + c * 16;
        cp_async16(dst, src);
    }
    asm volatile("cp.async.commit_group;" ::: "memory");
}

__global__ __launch_bounds__(256, 2)
void gemm_fp16(int mode, float* __restrict__ outp) {
    extern __shared__ char smem[];
    const uint32_t sb = smem_u32(smem);
    const int tid  = threadIdx.x;
    const int wid  = tid >> 5;
    const int lane = tid & 31;
    const int wm   = wid & 3;
    const int wn   = wid >> 2;

    const __half* A;
    const __half* B;
    float* C;
    int Ntot;
    if (mode == 0) { A = g_aexp;    B = g_wqkv_exp; C = g_qkv; Ntot = QKVN; }
    else           { A = g_ctx_exp; B = g_wo_exp;   C = outp;  Ntot = HID;  }

    const int bn = blockIdx.x * BN;
    const int bm = blockIdx.y * BM;

    float acc[2][8][4];
    #pragma unroll
    for (int mi = 0; mi < 2; mi++)
        #pragma unroll
        for (int ni = 0; ni < 8; ni++)
            #pragma unroll
            for (int q = 0; q < 4; q++) acc[mi][ni][q] = 0.f;

    const uint32_t a_off0 = (uint32_t)(wm * 32 +      (lane & 15)) * ROWB + (lane >> 4) * 16;
    const uint32_t a_off1 = (uint32_t)(wm * 32 + 16 + (lane & 15)) * ROWB + (lane >> 4) * 16;
    const uint32_t b_off  = (uint32_t)(wn * 64 + (lane & 7) + ((lane >> 4) & 1) * 8) * ROWB
                          + ((lane >> 3) & 1) * 16;

    load_stage(A, B, bm, bn, 0,  sb,          tid);
    load_stage(A, B, bm, bn, BK, sb + STAGEB, tid);

    #pragma unroll 1
    for (int i = 0; i < NCH; i++) {
        if (i < NCH - 1) asm volatile("cp.async.wait_group 1;" ::: "memory");
        else             asm volatile("cp.async.wait_group 0;" ::: "memory");
        __syncthreads();

        if (i + 2 < NCH) {
            int nb = (i + 2) % STAGES;
            load_stage(A, B, bm, bn, (i + 2) * BK, sb + nb * STAGEB, tid);
        }

        const uint32_t As = sb + (i % STAGES) * STAGEB;
        const uint32_t Bs = As + TILEB;

        #pragma unroll
        for (int ks = 0; ks < 4; ks++) {
            const uint32_t koff = ks * 32;
            uint32_t a[2][4];
            ldsm4(a[0], As + a_off0 + koff);
            ldsm4(a[1], As + a_off1 + koff);
            uint32_t b[4][4];
            #pragma unroll
            for (int p = 0; p < 4; p++)
                ldsm4(b[p], Bs + b_off + (uint32_t)p * (16 * ROWB) + koff);
            #pragma unroll
            for (int mi = 0; mi < 2; mi++)
                #pragma unroll
                for (int ni = 0; ni < 8; ni++)
                    mma16816h(acc[mi][ni], a[mi],
                              b[ni >> 1][(ni & 1) * 2], b[ni >> 1][(ni & 1) * 2 + 1]);
        }
    }

    const float inv = 1.0f / 1024.0f;
    const int crow = bm + wm * 32 + (lane >> 2);
    const int ccol = bn + wn * 64 + (lane & 3) * 2;
    #pragma unroll
    for (int mi = 0; mi < 2; mi++) {
        #pragma unroll
        for (int ni = 0; ni < 8; ni++) {
            float* p0 = C + (size_t)(crow + mi * 16)     * Ntot + ccol + ni * 8;
            float* p1 = C + (size_t)(crow + mi * 16 + 8) * Ntot + ccol + ni * 8;
            *(float2*)p0 = make_float2(acc[mi][ni][0] * inv, acc[mi][ni][1] * inv);
            *(float2*)p1 = make_float2(acc[mi][ni][2] * inv, acc[mi][ni][3] * inv);
        }
    }
}

// ---------------------------------------------------------------------------
// Cache copy + RoPE + scatters (unchanged)
// ---------------------------------------------------------------------------
__global__ void copy_caches(const float4* __restrict__ kc, const float4* __restrict__ vc,
                            float4* __restrict__ okc, float4* __restrict__ ovc, int n4) {
    int i = blockIdx.x * blockDim.x + threadIdx.x;
    if (i < n4) { okc[i] = kc[i]; ovc[i] = vc[i]; }
}

__global__ void rope_scatter(const float* __restrict__ cosb,
                             const float* __restrict__ sinb, const int* __restrict__ slots,
                             float* __restrict__ okc) {
    int idx = blockIdx.x * blockDim.x + threadIdx.x;
    if (idx >= TT * (NH + NKV) * ROT) return;
    int r    = idx & (ROT - 1);
    int head = (idx >> 6) % (NH + NKV);
    int t    = idx / (ROT * (NH + NKV));
    float c = cosb[t * ROT + r];
    float s = sinb[t * ROT + r];
    float* base = g_qkv + (size_t)t * QKVN + head * HD;
    float x1 = base[r];
    float x2 = base[r + ROT];
    float o1 = x1 * c - x2 * s;
    float o2 = x1 * s + x2 * c;
    base[r] = o1;
    base[r + ROT] = o2;
    if (head >= NH && okc != nullptr) {
        int kvh = head - NH;
        float* kcp = okc + (size_t)slots[t] * (NKV * HD) + kvh * HD;
        kcp[r] = o1;
        kcp[r + ROT] = o2;
    }
}

__global__ void v_scatter(const int* __restrict__ slots, float* __restrict__ ovc) {
    int idx = blockIdx.x * blockDim.x + threadIdx.x;
    if (idx >= TT * NKV * HD) return;
    int d   = idx & (HD - 1);
    int kvh = (idx >> 7) & (NKV - 1);
    int t   = idx >> 10;
    ovc[(size_t)slots[t] * (NKV * HD) + kvh * HD + d] =
        g_qkv[(size_t)t * QKVN + (NH + NKV) * HD + kvh * HD + d];
}

// ---------------------------------------------------------------------------
// Tensor-core flash attention — fp16 2-term split, fp32 accumulate.
// Q = [hi|lo] of (qscale*256*q); K,V = hi of 32*k / 32*v.
// S_mma = 8192 * logit -> unscale by 1/8192 before softmax (log2 domain).
// Epilogue writes g_ctx_exp directly: 32*ctx = acc / l (V's 32 cancels).
// Smem 102 KB -> 2 CTAs/SM.
// ---------------------------------------------------------------------------
#define ASTR 272
#define QH_OFF 0
#define QL_OFF (128 * ASTR)
#define KH_OFF (2 * 128 * ASTR)
#define VH_OFF (KH_OFF + 64 * ASTR)
#define ATT_SMEM (VH_OFF + 64 * ASTR)   // 104448

__global__ __launch_bounds__(256, 2)
void attn_mma() {
    extern __shared__ char sm[];
    const uint32_t sb = smem_u32(sm);
    const int qt  = blockIdx.x;
    const int h   = blockIdx.y;
    const int b   = blockIdx.z;
    const int kvh = h >> 2;
    const int tid  = threadIdx.x;
    const int wid  = tid >> 5;
    const int lane = tid & 31;
    // softmax scale * log2(e) * 256 (fp16 split headroom)
    const float qf = 0.08838834764831845f * 1.4426950408889634f * 256.0f;
    const float kf = 32.0f;

    // ---- load Q tile (128 x 128), scale + hi/lo fp16 split ----
    const float* qbase = g_qkv + (size_t)(b * SEQ + qt * 128) * QKVN + h * HD;
    for (int i = tid; i < 128 * 32; i += 256) {
        int r = i >> 5, c = i & 31;
        float4 v = *(const float4*)(qbase + (size_t)r * QKVN + c * 4);
        v.x *= qf; v.y *= qf; v.z *= qf; v.w *= qf;
        __half h0 = __float2half_rn(v.x), h1 = __float2half_rn(v.y);
        __half h2 = __float2half_rn(v.z), h3 = __float2half_rn(v.w);
        __half e0 = __float2half_rn(v.x - __half2float(h0));
        __half e1 = __float2half_rn(v.y - __half2float(h1));
        __half e2 = __float2half_rn(v.z - __half2float(h2));
        __half e3 = __float2half_rn(v.w - __half2float(h3));
        __half2* dh = (__half2*)(sm + QH_OFF + r * ASTR + c * 8);
        __half2* dl = (__half2*)(sm + QL_OFF + r * ASTR + c * 8);
        dh[0] = __half2(h0, h1); dh[1] = __half2(h2, h3);
        dl[0] = __half2(e0, e1); dl[1] = __half2(e2, e3);
    }

    float acc_o[16][4];
    #pragma unroll
    for (int f = 0; f < 16; f++)
        #pragma unroll
        for (int q = 0; q < 4; q++) acc_o[f][q] = 0.f;
    float m0 = -INFINITY, m1 = -INFINITY, l0 = 0.f, l1 = 0.f;

    const float* kb0 = g_qkv + (size_t)(b * SEQ) * QKVN + NH * HD + kvh * HD;
    const float* vb0 = kb0 + NKV * HD;
    const int qrow0 = qt * 128 + 16 * wid + (lane >> 2);

    const uint32_t a_off = (uint32_t)(16 * wid + (lane & 15)) * ASTR + (lane >> 4) * 16;
    const uint32_t kb_off = (uint32_t)((lane & 7) + ((lane >> 4) & 1) * 8) * ASTR
                          + ((lane >> 3) & 1) * 16;
    const uint32_t v_off = (uint32_t)(lane & 15) * ASTR + (lane >> 4) * 16;

    const int nkt = 2 * qt + 2;
    for (int kt = 0; kt < nkt; kt++) {
        __syncthreads();   // previous iteration done with K/V smem (and Q store)
        // ---- load K,V tile (64 x 128 each), fp16 hi only ----
        for (int i = tid; i < 64 * 32 * 2; i += 256) {
            int ten = i >> 11;                 // 0:K 1:V
            int r = (i >> 5) & 63, c = i & 31;
            const float* src = (ten ? vb0 : kb0) + (size_t)(kt * 64 + r) * QKVN + c * 4;
            float4 v = *(const float4*)src;
            __half h0 = __float2half_rn(v.x * kf), h1 = __float2half_rn(v.y * kf);
            __half h2 = __float2half_rn(v.z * kf), h3 = __float2half_rn(v.w * kf);
            int hof = (ten ? VH_OFF : KH_OFF) + r * ASTR + c * 8;
            __half2* dh = (__half2*)(sm + hof);
            dh[0] = __half2(h0, h1); dh[1] = __half2(h2, h3);
        }
        __syncthreads();

        // ---- S = Q K^T (2-term fp16), warp tile 16x64 ----
        float s[8][4];
        #pragma unroll
        for (int j = 0; j < 8; j++)
            #pragma unroll
            for (int q = 0; q < 4; q++) s[j][q] = 0.f;

        #pragma unroll
        for (int kk = 0; kk < 8; kk++) {
            uint32_t ah[4], al[4];
            ldsm4(ah, sb + QH_OFF + a_off + kk * 32);
            ldsm4(al, sb + QL_OFF + a_off + kk * 32);
            uint32_t bh[4][4];
            #pragma unroll
            for (int p = 0; p < 4; p++)
                ldsm4(bh[p], sb + KH_OFF + kb_off + (uint32_t)p * (16 * ASTR) + kk * 32);
            #pragma unroll
            for (int p = 0; p < 4; p++)
                #pragma unroll
                for (int q = 0; q < 2; q++) {
                    int j = p * 2 + q;
                    mma16816h(s[j], ah, bh[p][q * 2], bh[p][q * 2 + 1]);
                    mma16816h(s[j], al, bh[p][q * 2], bh[p][q * 2 + 1]);
                }
        }

        // unscale logits (log2 domain): / (256*32)
        const float su = 1.0f / 8192.0f;
        #pragma unroll
        for (int j = 0; j < 8; j++) {
            s[j][0] *= su; s[j][1] *= su; s[j][2] *= su; s[j][3] *= su;
        }

        // ---- causal mask (diagonal region) + row max ----
        if (kt >= 2 * qt) {
            #pragma unroll
            for (int j = 0; j < 8; j++) {
                int c0 = kt * 64 + 8 * j + 2 * (lane & 3);
                if (c0     > qrow0)     s[j][0] = -INFINITY;
                if (c0 + 1 > qrow0)     s[j][1] = -INFINITY;
                if (c0     > qrow0 + 8) s[j][2] = -INFINITY;
                if (c0 + 1 > qrow0 + 8) s[j][3] = -INFINITY;
            }
        }
        float tm0 = -INFINITY, tm1 = -INFINITY;
        #pragma unroll
        for (int j = 0; j < 8; j++) {
            tm0 = fmaxf(tm0, fmaxf(s[j][0], s[j][1]));
            tm1 = fmaxf(tm1, fmaxf(s[j][2], s[j][3]));
        }
        tm0 = fmaxf(tm0, __shfl_xor_sync(0xffffffffu, tm0, 1));
        tm0 = fmaxf(tm0, __shfl_xor_sync(0xffffffffu, tm0, 2));
        tm1 = fmaxf(tm1, __shfl_xor_sync(0xffffffffu, tm1, 1));
        tm1 = fmaxf(tm1, __shfl_xor_sync(0xffffffffu, tm1, 2));
        float mn0 = fmaxf(m0, tm0), mn1 = fmaxf(m1, tm1);
        float sc0 = exp2f(m0 - mn0), sc1 = exp2f(m1 - mn1);

        // ---- P = exp2(S - m), fp16 hi/lo A-fragments, partial row sums ----
        uint32_t ap[4][4], apl[4][4];
        float ps0 = 0.f, ps1 = 0.f;
        #pragma unroll
        for (int t = 0; t < 4; t++) {
            #pragma unroll
            for (int q = 0; q < 2; q++) {
                int j = t * 2 + q;
                float p0 = exp2f(s[j][0] - mn0);
                float p1 = exp2f(s[j][1] - mn0);
                float p2 = exp2f(s[j][2] - mn1);
                float p3 = exp2f(s[j][3] - mn1);
                ps0 += p0 + p1; ps1 += p2 + p3;
                uint32_t hh0 = packh2(p0, p1), hh1 = packh2(p2, p3);
                __half2 hv0 = *(__half2*)&hh0;
                __half2 hv1 = *(__half2*)&hh1;
                uint32_t ll0 = packh2(p0 - __half2float(hv0.x),
                                      p1 - __half2float(hv0.y));
                uint32_t ll1 = packh2(p2 - __half2float(hv1.x),
                                      p3 - __half2float(hv1.y));
                ap[t][q * 2]      = hh0;
                ap[t][q * 2 + 1]  = hh1;
                apl[t][q * 2]     = ll0;
                apl[t][q * 2 + 1] = ll1;
            }
        }
        ps0 += __shfl_xor_sync(0xffffffffu, ps0, 1);
        ps0 += __shfl_xor_sync(0xffffffffu, ps0, 2);
        ps1 += __shfl_xor_sync(0xffffffffu, ps1, 1);
        ps1 += __shfl_xor_sync(0xffffffffu, ps1, 2);
        l0 = l0 * sc0 + ps0;
        l1 = l1 * sc1 + ps1;
        m0 = mn0; m1 = mn1;

        // ---- rescale O ----
        #pragma unroll
        for (int f = 0; f < 16; f++) {
            acc_o[f][0] *= sc0; acc_o[f][1] *= sc0;
            acc_o[f][2] *= sc1; acc_o[f][3] *= sc1;
        }

        // ---- O += P V (2-term fp16) ----
        #pragma unroll
        for (int t = 0; t < 4; t++) {
            #pragma unroll
            for (int db = 0; db < 8; db++) {
                uint32_t bv[4];
                ldsm4t(bv, sb + VH_OFF + v_off + (uint32_t)t * (16 * ASTR) + db * 32);
                mma16816h(acc_o[db * 2],     ap[t],  bv[0], bv[1]);
                mma16816h(acc_o[db * 2 + 1], ap[t],  bv[2], bv[3]);
                mma16816h(acc_o[db * 2],     apl[t], bv[0], bv[1]);
                mma16816h(acc_o[db * 2 + 1], apl[t], bv[2], bv[3]);
            }
        }
    }

    // ---- epilogue: write 32*ctx = acc / l directly as fp16 hi/lo ----
    float inv0 = 1.f / l0, inv1 = 1.f / l1;
    const size_t row0 = (size_t)(b * SEQ + qrow0);
    const int col0 = h * HD + 2 * (lane & 3);
    #pragma unroll
    for (int f = 0; f < 16; f++) {
        int col = col0 + 8 * f;
        {
            float v0 = acc_o[f][0] * inv0, v1 = acc_o[f][1] * inv0;
            __half h0 = __float2half_rn(v0), h1 = __float2half_rn(v1);
            __half e0 = __float2half_rn(v0 - __half2float(h0));
            __half e1 = __float2half_rn(v1 - __half2float(h1));
            *(__half2*)(g_ctx_exp + row0 * KPA + col)        = __half2(h0, h1);
            *(__half2*)(g_ctx_exp + row0 * KPA + KTOT + col) = __half2(e0, e1);
        }
        {
            float v0 = acc_o[f][2] * inv1, v1 = acc_o[f][3] * inv1;
            __half h0 = __float2half_rn(v0), h1 = __float2half_rn(v1);
            __half e0 = __float2half_rn(v0 - __half2float(h0));
            __half e1 = __float2half_rn(v1 - __half2float(h1));
            *(__half2*)(g_ctx_exp + (row0 + 8) * KPA + col)        = __half2(h0, h1);
            *(__half2*)(g_ctx_exp + (row0 + 8) * KPA + KTOT + col) = __half2(e0, e1);
        }
    }
}

// ---------------------------------------------------------------------------
extern "C" void kernel_launch(void* const* d_in, const int* in_sizes, int n_in,
                              void* d_out, int out_size) {
    const float* hidden = (const float*)d_in[0];
    const float* cosb   = (const float*)d_in[1];
    const float* sinb   = (const float*)d_in[2];
    const float* wqkv   = (const float*)d_in[3];
    const float* wo     = (const float*)d_in[4];
    const float* kc_in  = (const float*)d_in[5];
    const float* vc_in  = (const float*)d_in[6];
    const int*   slots  = (const int*)d_in[7];
    float* out = (float*)d_out;

    const size_t out_elems   = (size_t)TT * HID;
    const size_t cache_elems = (size_t)NSLOTS * NKV * HD;
    float* okc = nullptr;
    float* ovc = nullptr;
    if ((size_t)out_size >= out_elems + 2 * cache_elems) {
        okc = out + out_elems;
        ovc = okc + cache_elems;
    }

    cudaFuncSetAttribute(gemm_fp16, cudaFuncAttributeMaxDynamicSharedMemorySize, GEMM_SMEM);
    cudaFuncSetAttribute(attn_mma, cudaFuncAttributeMaxDynamicSharedMemorySize, ATT_SMEM);

    if (okc) {
        int n4 = (int)(cache_elems / 4);
        copy_caches<<<(n4 + 255) / 256, 256>>>((const float4*)kc_in, (const float4*)vc_in,
                                               (float4*)okc, (float4*)ovc, n4);
    }

    // expand operands for QKV GEMM
    expand2<<<(TT   * (KTOT / 4) + 255) / 256, 256>>>(hidden, TT,   0);
    expand2<<<(QKVN * (KTOT / 4) + 255) / 256, 256>>>(wqkv,   QKVN, 1);

    // 1) QKV projection -> g_qkv
    gemm_fp16<<<dim3(QKVN / BN, TT / BM), 256, GEMM_SMEM>>>(0, nullptr);

    // 2) RoPE + k scatter
    {
        int n = TT * (NH + NKV) * ROT;
        rope_scatter<<<(n + 255) / 256, 256>>>(cosb, sinb, slots, okc);
    }
    // 3) v scatter
    if (ovc) {
        v_scatter<<<(TT * NKV * HD + 255) / 256, 256>>>(slots, ovc);
    }

    // 4) attention -> g_ctx_exp (fp16 hi/lo, ready for O-proj)
    attn_mma<<<dim3(SEQ / 128, NH, BATCH), 256, ATT_SMEM>>>();

    // 5) expand w_o, then O projection -> d_out
    expand2<<<(HID * (KTOT / 4) + 255) / 256, 256>>>(wo, HID, 2);
    gemm_fp16<<<dim3(HID / BN, TT / BM), 256, GEMM_SMEM>>>(1, out);
}

// round 17
// speedup vs baseline: 2.4118x; 1.1779x over previous
#include <cuda_runtime.h>
#include <cuda_bf16.h>
#include <cuda_fp16.h>
#include <math.h>
#include <stdint.h>

#define TT     4096      // total tokens B*S
#define SEQ    1024
#define BATCH  4
#define HID    4096
#define NH     32
#define NKV    8
#define HD     128
#define QKVN   6144      // NH*HD + 2*NKV*HD
#define NSLOTS 8192
#define ROT    64
#define KTOT   4096      // logical GEMM K (= HID)
#define KPA    8192      // expanded A row: [hi | lo] fp16

// ---------------------------------------------------------------------------
// Scratch (no cudaMalloc allowed)
// ---------------------------------------------------------------------------
__device__ float g_qkv[(size_t)TT * QKVN];              // fp32 qkv activations
__device__ __half g_aexp    [(size_t)TT   * KPA];       // hidden*32  [hi|lo]
__device__ __half g_ctx_exp [(size_t)TT   * KPA];       // ctx*32     [hi] (stride KTOT)
__device__ __half g_wqkv_exp[(size_t)QKVN * KTOT];      // w_qkv*32   [hi]
__device__ __half g_wo_exp  [(size_t)HID  * KTOT];      // w_o*32     [hi]

// ---------------------------------------------------------------------------
// helpers
// ---------------------------------------------------------------------------
__device__ __forceinline__ uint32_t smem_u32(const void* p) {
    uint32_t a;
    asm("{ .reg .u64 t; cvta.to.shared.u64 t, %1; cvt.u32.u64 %0, t; }" : "=r"(a) : "l"(p));
    return a;
}
__device__ __forceinline__ void cp_async16(uint32_t dst, const void* src) {
    asm volatile("cp.async.cg.shared.global [%0], [%1], 16;" :: "r"(dst), "l"(src));
}
__device__ __forceinline__ void ldsm4(uint32_t* r, uint32_t addr) {
    asm volatile("ldmatrix.sync.aligned.m8n8.x4.shared.b16 {%0,%1,%2,%3}, [%4];"
        : "=r"(r[0]), "=r"(r[1]), "=r"(r[2]), "=r"(r[3]) : "r"(addr));
}
__device__ __forceinline__ void ldsm4t(uint32_t* r, uint32_t addr) {
    asm volatile("ldmatrix.sync.aligned.m8n8.x4.trans.shared.b16 {%0,%1,%2,%3}, [%4];"
        : "=r"(r[0]), "=r"(r[1]), "=r"(r[2]), "=r"(r[3]) : "r"(addr));
}
// fp16 mma
__device__ __forceinline__ void mma16816h(float* c, const uint32_t* a, uint32_t b0, uint32_t b1) {
    asm volatile(
        "mma.sync.aligned.m16n8k16.row.col.f32.f16.f16.f32 "
        "{%0,%1,%2,%3}, {%4,%5,%6,%7}, {%8,%9}, {%0,%1,%2,%3};"
        : "+f"(c[0]), "+f"(c[1]), "+f"(c[2]), "+f"(c[3])
        : "r"(a[0]), "r"(a[1]), "r"(a[2]), "r"(a[3]), "r"(b0), "r"(b1));
}
__device__ __forceinline__ uint32_t packh2(float lo, float hi) {
    __half2 v(__float2half_rn(lo), __float2half_rn(hi));
    return *(uint32_t*)&v;
}

// ---------------------------------------------------------------------------
// fp32 -> fp16 split expansion (scaled by 32)
// mode: 0 hidden->g_aexp (A-type: [hi|lo]), 1 wqkv->g_wqkv_exp (B: [hi]),
//       2 wo->g_wo_exp (B: [hi])
// ---------------------------------------------------------------------------
__global__ void expand2(const float* __restrict__ src, int rows, int mode) {
    int idx = blockIdx.x * blockDim.x + threadIdx.x;
    int total = rows * (KTOT / 4);
    if (idx >= total) return;
    int row = idx >> 10;
    int c4  = idx & 1023;
    float4 v = *(const float4*)(src + (size_t)row * KTOT + c4 * 4);
    const float sc = 32.0f;
    float a0 = v.x * sc, a1 = v.y * sc, a2 = v.z * sc, a3 = v.w * sc;
    __half h0 = __float2half_rn(a0), h1 = __float2half_rn(a1);
    __half h2 = __float2half_rn(a2), h3 = __float2half_rn(a3);
    if (mode == 0) {
        __half l0 = __float2half_rn(a0 - __half2float(h0));
        __half l1 = __float2half_rn(a1 - __half2float(h1));
        __half l2 = __float2half_rn(a2 - __half2float(h2));
        __half l3 = __float2half_rn(a3 - __half2float(h3));
        size_t base = (size_t)row * KPA + c4 * 4;
        __half2* dh = (__half2*)(g_aexp + base);
        __half2* dl = (__half2*)(g_aexp + base + KTOT);
        dh[0] = __half2(h0, h1); dh[1] = __half2(h2, h3);
        dl[0] = __half2(l0, l1); dl[1] = __half2(l2, l3);
    } else {
        __half* dst = (mode == 1) ? g_wqkv_exp : g_wo_exp;
        size_t base = (size_t)row * KTOT + c4 * 4;
        __half2* dh = (__half2*)(dst + base);
        dh[0] = __half2(h0, h1); dh[1] = __half2(h2, h3);
    }
}

// ---------------------------------------------------------------------------
// fp16 mma.sync GEMM: C = (1/1024) * A'[M, ka] @ B'[N, KTOT ring]^T
// ka = KPA (QKV: A=[hi|lo], B ring re-reads hi) or KTOT (O-proj: 1-term).
// CTA 128x128, BK=64, 3-stage cp.async pipeline, 8 warps 4(M)x2(N) -> 32x64.
// ---------------------------------------------------------------------------
#define BM 128
#define BN 128
#define BK 64
#define STAGES 3
#define ROWB 144
#define TILEB (128 * ROWB)
#define STAGEB (2 * TILEB)
#define GEMM_SMEM (STAGES * STAGEB)

__device__ __forceinline__ void load_stage(const __half* __restrict__ A,
                                           const __half* __restrict__ B,
                                           int bm, int bn, int k0, int ka,
                                           uint32_t stage_base, int tid) {
    const int kb = k0 & (KTOT - 1);        // B ring: reuse hi segment
    #pragma unroll
    for (int it = 0; it < 8; it++) {
        int idx = tid + it * 256;
        int tile = idx >> 10;
        int r = (idx >> 3) & 127;
        int c = idx & 7;
        const __half* src =
            tile ? (B + (size_t)(bn + r) * KTOT + kb + c * 8)
                 : (A + (size_t)(bm + r) * ka   + k0 + c * 8);
        uint32_t dst = stage_base + tile * TILEB + r * ROWB + c * 16;
        cp_async16(dst, src);
    }
    asm volatile("cp.async.commit_group;" ::: "memory");
}

__global__ __launch_bounds__(256, 2)
void gemm_fp16(int mode, int ka, float* __restrict__ outp) {
    extern __shared__ char smem[];
    const uint32_t sb = smem_u32(smem);
    const int tid  = threadIdx.x;
    const int wid  = tid >> 5;
    const int lane = tid & 31;
    const int wm   = wid & 3;
    const int wn   = wid >> 2;

    const __half* A;
    const __half* B;
    float* C;
    int Ntot;
    if (mode == 0) { A = g_aexp;    B = g_wqkv_exp; C = g_qkv; Ntot = QKVN; }
    else           { A = g_ctx_exp; B = g_wo_exp;   C = outp;  Ntot = HID;  }

    const int bn = blockIdx.x * BN;
    const int bm = blockIdx.y * BM;
    const int nch = ka / BK;

    float acc[2][8][4];
    #pragma unroll
    for (int mi = 0; mi < 2; mi++)
        #pragma unroll
        for (int ni = 0; ni < 8; ni++)
            #pragma unroll
            for (int q = 0; q < 4; q++) acc[mi][ni][q] = 0.f;

    const uint32_t a_off0 = (uint32_t)(wm * 32 +      (lane & 15)) * ROWB + (lane >> 4) * 16;
    const uint32_t a_off1 = (uint32_t)(wm * 32 + 16 + (lane & 15)) * ROWB + (lane >> 4) * 16;
    const uint32_t b_off  = (uint32_t)(wn * 64 + (lane & 7) + ((lane >> 4) & 1) * 8) * ROWB
                          + ((lane >> 3) & 1) * 16;

    load_stage(A, B, bm, bn, 0,  ka, sb,          tid);
    load_stage(A, B, bm, bn, BK, ka, sb + STAGEB, tid);

    #pragma unroll 1
    for (int i = 0; i < nch; i++) {
        if (i < nch - 1) asm volatile("cp.async.wait_group 1;" ::: "memory");
        else             asm volatile("cp.async.wait_group 0;" ::: "memory");
        __syncthreads();

        if (i + 2 < nch) {
            int nb = (i + 2) % STAGES;
            load_stage(A, B, bm, bn, (i + 2) * BK, ka, sb + nb * STAGEB, tid);
        }

        const uint32_t As = sb + (i % STAGES) * STAGEB;
        const uint32_t Bs = As + TILEB;

        #pragma unroll
        for (int ks = 0; ks < 4; ks++) {
            const uint32_t koff = ks * 32;
            uint32_t a[2][4];
            ldsm4(a[0], As + a_off0 + koff);
            ldsm4(a[1], As + a_off1 + koff);
            uint32_t b[4][4];
            #pragma unroll
            for (int p = 0; p < 4; p++)
                ldsm4(b[p], Bs + b_off + (uint32_t)p * (16 * ROWB) + koff);
            #pragma unroll
            for (int mi = 0; mi < 2; mi++)
                #pragma unroll
                for (int ni = 0; ni < 8; ni++)
                    mma16816h(acc[mi][ni], a[mi],
                              b[ni >> 1][(ni & 1) * 2], b[ni >> 1][(ni & 1) * 2 + 1]);
        }
    }

    const float inv = 1.0f / 1024.0f;
    const int crow = bm + wm * 32 + (lane >> 2);
    const int ccol = bn + wn * 64 + (lane & 3) * 2;
    #pragma unroll
    for (int mi = 0; mi < 2; mi++) {
        #pragma unroll
        for (int ni = 0; ni < 8; ni++) {
            float* p0 = C + (size_t)(crow + mi * 16)     * Ntot + ccol + ni * 8;
            float* p1 = C + (size_t)(crow + mi * 16 + 8) * Ntot + ccol + ni * 8;
            *(float2*)p0 = make_float2(acc[mi][ni][0] * inv, acc[mi][ni][1] * inv);
            *(float2*)p1 = make_float2(acc[mi][ni][2] * inv, acc[mi][ni][3] * inv);
        }
    }
}

// ---------------------------------------------------------------------------
// Cache copy + RoPE + scatters (unchanged)
// ---------------------------------------------------------------------------
__global__ void copy_caches(const float4* __restrict__ kc, const float4* __restrict__ vc,
                            float4* __restrict__ okc, float4* __restrict__ ovc, int n4) {
    int i = blockIdx.x * blockDim.x + threadIdx.x;
    if (i < n4) { okc[i] = kc[i]; ovc[i] = vc[i]; }
}

__global__ void rope_scatter(const float* __restrict__ cosb,
                             const float* __restrict__ sinb, const int* __restrict__ slots,
                             float* __restrict__ okc) {
    int idx = blockIdx.x * blockDim.x + threadIdx.x;
    if (idx >= TT * (NH + NKV) * ROT) return;
    int r    = idx & (ROT - 1);
    int head = (idx >> 6) % (NH + NKV);
    int t    = idx / (ROT * (NH + NKV));
    float c = cosb[t * ROT + r];
    float s = sinb[t * ROT + r];
    float* base = g_qkv + (size_t)t * QKVN + head * HD;
    float x1 = base[r];
    float x2 = base[r + ROT];
    float o1 = x1 * c - x2 * s;
    float o2 = x1 * s + x2 * c;
    base[r] = o1;
    base[r + ROT] = o2;
    if (head >= NH && okc != nullptr) {
        int kvh = head - NH;
        float* kcp = okc + (size_t)slots[t] * (NKV * HD) + kvh * HD;
        kcp[r] = o1;
        kcp[r + ROT] = o2;
    }
}

__global__ void v_scatter(const int* __restrict__ slots, float* __restrict__ ovc) {
    int idx = blockIdx.x * blockDim.x + threadIdx.x;
    if (idx >= TT * NKV * HD) return;
    int d   = idx & (HD - 1);
    int kvh = (idx >> 7) & (NKV - 1);
    int t   = idx >> 10;
    ovc[(size_t)slots[t] * (NKV * HD) + kvh * HD + d] =
        g_qkv[(size_t)t * QKVN + (NH + NKV) * HD + kvh * HD + d];
}

// ---------------------------------------------------------------------------
// Tensor-core flash attention — fp16 2-term split, fp32 accumulate.
// Q = [hi|lo] of (qscale*256*q); K,V = hi of 32*k / 32*v.
// Heavy q-tiles first (qt reversed) for wave load balance.
// Epilogue writes g_ctx_exp hi only (stride KTOT): 32*ctx = acc / l.
// ---------------------------------------------------------------------------
#define ASTR 272
#define QH_OFF 0
#define QL_OFF (128 * ASTR)
#define KH_OFF (2 * 128 * ASTR)
#define VH_OFF (KH_OFF + 64 * ASTR)
#define ATT_SMEM (VH_OFF + 64 * ASTR)   // 104448

__global__ __launch_bounds__(256, 2)
void attn_mma() {
    extern __shared__ char sm[];
    const uint32_t sb = smem_u32(sm);
    const int qt  = (int)gridDim.x - 1 - (int)blockIdx.x;   // heavy tiles first
    const int h   = blockIdx.y;
    const int b   = blockIdx.z;
    const int kvh = h >> 2;
    const int tid  = threadIdx.x;
    const int wid  = tid >> 5;
    const int lane = tid & 31;
    // softmax scale * log2(e) * 256 (fp16 split headroom)
    const float qf = 0.08838834764831845f * 1.4426950408889634f * 256.0f;
    const float kf = 32.0f;

    // ---- load Q tile (128 x 128), scale + hi/lo fp16 split ----
    const float* qbase = g_qkv + (size_t)(b * SEQ + qt * 128) * QKVN + h * HD;
    for (int i = tid; i < 128 * 32; i += 256) {
        int r = i >> 5, c = i & 31;
        float4 v = *(const float4*)(qbase + (size_t)r * QKVN + c * 4);
        v.x *= qf; v.y *= qf; v.z *= qf; v.w *= qf;
        __half h0 = __float2half_rn(v.x), h1 = __float2half_rn(v.y);
        __half h2 = __float2half_rn(v.z), h3 = __float2half_rn(v.w);
        __half e0 = __float2half_rn(v.x - __half2float(h0));
        __half e1 = __float2half_rn(v.y - __half2float(h1));
        __half e2 = __float2half_rn(v.z - __half2float(h2));
        __half e3 = __float2half_rn(v.w - __half2float(h3));
        __half2* dh = (__half2*)(sm + QH_OFF + r * ASTR + c * 8);
        __half2* dl = (__half2*)(sm + QL_OFF + r * ASTR + c * 8);
        dh[0] = __half2(h0, h1); dh[1] = __half2(h2, h3);
        dl[0] = __half2(e0, e1); dl[1] = __half2(e2, e3);
    }

    float acc_o[16][4];
    #pragma unroll
    for (int f = 0; f < 16; f++)
        #pragma unroll
        for (int q = 0; q < 4; q++) acc_o[f][q] = 0.f;
    float m0 = -INFINITY, m1 = -INFINITY, l0 = 0.f, l1 = 0.f;

    const float* kb0 = g_qkv + (size_t)(b * SEQ) * QKVN + NH * HD + kvh * HD;
    const float* vb0 = kb0 + NKV * HD;
    const int qrow0 = qt * 128 + 16 * wid + (lane >> 2);

    const uint32_t a_off = (uint32_t)(16 * wid + (lane & 15)) * ASTR + (lane >> 4) * 16;
    const uint32_t kb_off = (uint32_t)((lane & 7) + ((lane >> 4) & 1) * 8) * ASTR
                          + ((lane >> 3) & 1) * 16;
    const uint32_t v_off = (uint32_t)(lane & 15) * ASTR + (lane >> 4) * 16;

    const int nkt = 2 * qt + 2;
    for (int kt = 0; kt < nkt; kt++) {
        __syncthreads();   // previous iteration done with K/V smem (and Q store)
        // ---- load K,V tile (64 x 128 each), fp16 hi only ----
        for (int i = tid; i < 64 * 32 * 2; i += 256) {
            int ten = i >> 11;                 // 0:K 1:V
            int r = (i >> 5) & 63, c = i & 31;
            const float* src = (ten ? vb0 : kb0) + (size_t)(kt * 64 + r) * QKVN + c * 4;
            float4 v = *(const float4*)src;
            __half h0 = __float2half_rn(v.x * kf), h1 = __float2half_rn(v.y * kf);
            __half h2 = __float2half_rn(v.z * kf), h3 = __float2half_rn(v.w * kf);
            int hof = (ten ? VH_OFF : KH_OFF) + r * ASTR + c * 8;
            __half2* dh = (__half2*)(sm + hof);
            dh[0] = __half2(h0, h1); dh[1] = __half2(h2, h3);
        }
        __syncthreads();

        // ---- S = Q K^T (2-term fp16), warp tile 16x64 ----
        float s[8][4];
        #pragma unroll
        for (int j = 0; j < 8; j++)
            #pragma unroll
            for (int q = 0; q < 4; q++) s[j][q] = 0.f;

        #pragma unroll
        for (int kk = 0; kk < 8; kk++) {
            uint32_t ah[4], al[4];
            ldsm4(ah, sb + QH_OFF + a_off + kk * 32);
            ldsm4(al, sb + QL_OFF + a_off + kk * 32);
            uint32_t bh[4][4];
            #pragma unroll
            for (int p = 0; p < 4; p++)
                ldsm4(bh[p], sb + KH_OFF + kb_off + (uint32_t)p * (16 * ASTR) + kk * 32);
            #pragma unroll
            for (int p = 0; p < 4; p++)
                #pragma unroll
                for (int q = 0; q < 2; q++) {
                    int j = p * 2 + q;
                    mma16816h(s[j], ah, bh[p][q * 2], bh[p][q * 2 + 1]);
                    mma16816h(s[j], al, bh[p][q * 2], bh[p][q * 2 + 1]);
                }
        }

        // unscale logits (log2 domain): / (256*32)
        const float su = 1.0f / 8192.0f;
        #pragma unroll
        for (int j = 0; j < 8; j++) {
            s[j][0] *= su; s[j][1] *= su; s[j][2] *= su; s[j][3] *= su;
        }

        // ---- causal mask (diagonal region) + row max ----
        if (kt >= 2 * qt) {
            #pragma unroll
            for (int j = 0; j < 8; j++) {
                int c0 = kt * 64 + 8 * j + 2 * (lane & 3);
                if (c0     > qrow0)     s[j][0] = -INFINITY;
                if (c0 + 1 > qrow0)     s[j][1] = -INFINITY;
                if (c0     > qrow0 + 8) s[j][2] = -INFINITY;
                if (c0 + 1 > qrow0 + 8) s[j][3] = -INFINITY;
            }
        }
        float tm0 = -INFINITY, tm1 = -INFINITY;
        #pragma unroll
        for (int j = 0; j < 8; j++) {
            tm0 = fmaxf(tm0, fmaxf(s[j][0], s[j][1]));
            tm1 = fmaxf(tm1, fmaxf(s[j][2], s[j][3]));
        }
        tm0 = fmaxf(tm0, __shfl_xor_sync(0xffffffffu, tm0, 1));
        tm0 = fmaxf(tm0, __shfl_xor_sync(0xffffffffu, tm0, 2));
        tm1 = fmaxf(tm1, __shfl_xor_sync(0xffffffffu, tm1, 1));
        tm1 = fmaxf(tm1, __shfl_xor_sync(0xffffffffu, tm1, 2));
        float mn0 = fmaxf(m0, tm0), mn1 = fmaxf(m1, tm1);
        float sc0 = exp2f(m0 - mn0), sc1 = exp2f(m1 - mn1);

        // ---- P = exp2(S - m), fp16 hi/lo A-fragments, partial row sums ----
        uint32_t ap[4][4], apl[4][4];
        float ps0 = 0.f, ps1 = 0.f;
        #pragma unroll
        for (int t = 0; t < 4; t++) {
            #pragma unroll
            for (int q = 0; q < 2; q++) {
                int j = t * 2 + q;
                float p0 = exp2f(s[j][0] - mn0);
                float p1 = exp2f(s[j][1] - mn0);
                float p2 = exp2f(s[j][2] - mn1);
                float p3 = exp2f(s[j][3] - mn1);
                ps0 += p0 + p1; ps1 += p2 + p3;
                uint32_t hh0 = packh2(p0, p1), hh1 = packh2(p2, p3);
                __half2 hv0 = *(__half2*)&hh0;
                __half2 hv1 = *(__half2*)&hh1;
                uint32_t ll0 = packh2(p0 - __half2float(hv0.x),
                                      p1 - __half2float(hv0.y));
                uint32_t ll1 = packh2(p2 - __half2float(hv1.x),
                                      p3 - __half2float(hv1.y));
                ap[t][q * 2]      = hh0;
                ap[t][q * 2 + 1]  = hh1;
                apl[t][q * 2]     = ll0;
                apl[t][q * 2 + 1] = ll1;
            }
        }
        ps0 += __shfl_xor_sync(0xffffffffu, ps0, 1);
        ps0 += __shfl_xor_sync(0xffffffffu, ps0, 2);
        ps1 += __shfl_xor_sync(0xffffffffu, ps1, 1);
        ps1 += __shfl_xor_sync(0xffffffffu, ps1, 2);
        l0 = l0 * sc0 + ps0;
        l1 = l1 * sc1 + ps1;
        m0 = mn0; m1 = mn1;

        // ---- rescale O ----
        #pragma unroll
        for (int f = 0; f < 16; f++) {
            acc_o[f][0] *= sc0; acc_o[f][1] *= sc0;
            acc_o[f][2] *= sc1; acc_o[f][3] *= sc1;
        }

        // ---- O += P V (2-term fp16) ----
        #pragma unroll
        for (int t = 0; t < 4; t++) {
            #pragma unroll
            for (int db = 0; db < 8; db++) {
                uint32_t bv[4];
                ldsm4t(bv, sb + VH_OFF + v_off + (uint32_t)t * (16 * ASTR) + db * 32);
                mma16816h(acc_o[db * 2],     ap[t],  bv[0], bv[1]);
                mma16816h(acc_o[db * 2 + 1], ap[t],  bv[2], bv[3]);
                mma16816h(acc_o[db * 2],     apl[t], bv[0], bv[1]);
                mma16816h(acc_o[db * 2 + 1], apl[t], bv[2], bv[3]);
            }
        }
    }

    // ---- epilogue: write 32*ctx = acc / l as fp16 hi (stride KTOT) ----
    float inv0 = 1.f / l0, inv1 = 1.f / l1;
    const size_t row0 = (size_t)(b * SEQ + qrow0);
    const int col0 = h * HD + 2 * (lane & 3);
    #pragma unroll
    for (int f = 0; f < 16; f++) {
        int col = col0 + 8 * f;
        {
            float v0 = acc_o[f][0] * inv0, v1 = acc_o[f][1] * inv0;
            *(__half2*)(g_ctx_exp + row0 * KTOT + col) =
                __half2(__float2half_rn(v0), __float2half_rn(v1));
        }
        {
            float v0 = acc_o[f][2] * inv1, v1 = acc_o[f][3] * inv1;
            *(__half2*)(g_ctx_exp + (row0 + 8) * KTOT + col) =
                __half2(__float2half_rn(v0), __float2half_rn(v1));
        }
    }
}

// ---------------------------------------------------------------------------
extern "C" void kernel_launch(void* const* d_in, const int* in_sizes, int n_in,
                              void* d_out, int out_size) {
    const float* hidden = (const float*)d_in[0];
    const float* cosb   = (const float*)d_in[1];
    const float* sinb   = (const float*)d_in[2];
    const float* wqkv   = (const float*)d_in[3];
    const float* wo     = (const float*)d_in[4];
    const float* kc_in  = (const float*)d_in[5];
    const float* vc_in  = (const float*)d_in[6];
    const int*   slots  = (const int*)d_in[7];
    float* out = (float*)d_out;

    const size_t out_elems   = (size_t)TT * HID;
    const size_t cache_elems = (size_t)NSLOTS * NKV * HD;
    float* okc = nullptr;
    float* ovc = nullptr;
    if ((size_t)out_size >= out_elems + 2 * cache_elems) {
        okc = out + out_elems;
        ovc = okc + cache_elems;
    }

    cudaFuncSetAttribute(gemm_fp16, cudaFuncAttributeMaxDynamicSharedMemorySize, GEMM_SMEM);
    cudaFuncSetAttribute(attn_mma, cudaFuncAttributeMaxDynamicSharedMemorySize, ATT_SMEM);

    if (okc) {
        int n4 = (int)(cache_elems / 4);
        copy_caches<<<(n4 + 255) / 256, 256>>>((const float4*)kc_in, (const float4*)vc_in,
                                               (float4*)okc, (float4*)ovc, n4);
    }

    // expand operands for QKV GEMM
    expand2<<<(TT   * (KTOT / 4) + 255) / 256, 256>>>(hidden, TT,   0);
    expand2<<<(QKVN * (KTOT / 4) + 255) / 256, 256>>>(wqkv,   QKVN, 1);

    // 1) QKV projection -> g_qkv (2-term fp16, ka = KPA)
    gemm_fp16<<<dim3(QKVN / BN, TT / BM), 256, GEMM_SMEM>>>(0, KPA, nullptr);

    // 2) RoPE + k scatter
    {
        int n = TT * (NH + NKV) * ROT;
        rope_scatter<<<(n + 255) / 256, 256>>>(cosb, sinb, slots, okc);
    }
    // 3) v scatter
    if (ovc) {
        v_scatter<<<(TT * NKV * HD + 255) / 256, 256>>>(slots, ovc);
    }

    // 4) attention -> g_ctx_exp (fp16 hi, stride KTOT)
    attn_mma<<<dim3(SEQ / 128, NH, BATCH), 256, ATT_SMEM>>>();

    // 5) expand w_o, then O projection -> d_out (1-term fp16, ka = KTOT)
    expand2<<<(HID * (KTOT / 4) + 255) / 256, 256>>>(wo, HID, 2);
    gemm_fp16<<<dim3(HID / BN, TT / BM), 256, GEMM_SMEM>>>(1, KTOT, out);
}